// round 1
// baseline (speedup 1.0000x reference)
#include <cuda_runtime.h>

#define CW 2048
#define DIM 128
#define BATCH 8

typedef unsigned long long ull;

// Scratch for projected+rotated Q/K and V (8 MB each; static __device__ per rules)
__device__ float g_q[BATCH * CW * DIM];
__device__ float g_k[BATCH * CW * DIM];
__device__ float g_v[BATCH * CW * DIM];

// ---------- packed fp32x2 helpers (Blackwell-only PTX; doubles FFMA throughput) ----------
__device__ __forceinline__ ull ld2(const float* p) {
    return *reinterpret_cast<const ull*>(p);
}
__device__ __forceinline__ void st2(float* p, ull v) {
    *reinterpret_cast<ull*>(p) = v;
}
__device__ __forceinline__ void ffma2(ull& d, ull a, ull b) {
    asm("fma.rn.f32x2 %0, %1, %2, %0;" : "+l"(d) : "l"(a), "l"(b));
}
__device__ __forceinline__ ull fmul2(ull a, ull b) {
    ull r; asm("mul.rn.f32x2 %0, %1, %2;" : "=l"(r) : "l"(a), "l"(b)); return r;
}
__device__ __forceinline__ ull fpack2(float lo, float hi) {
    ull r; asm("mov.b64 %0, {%1, %2};" : "=l"(r) : "f"(lo), "f"(hi)); return r;
}
__device__ __forceinline__ float2 funpack2(ull v) {
    float lo, hi; asm("mov.b64 {%0, %1}, %2;" : "=f"(lo), "=f"(hi) : "l"(v));
    return make_float2(lo, hi);
}

// ============================================================================
// Kernel A: fused QKV projection + RoPE (reads only the 2x2-block diag of R)
//   q[b,m,e] = sum_d x[b,m,d] * W[e,d];  rotate (q[2i],q[2i+1]) by (c,s) from R
// ============================================================================
#define XS_ST 130
#define WS_ST 130
#define CS_ST 65
#define SMEM_A ((64 * XS_ST + 128 * WS_ST + 2 * 64 * CS_ST) * 4)

__global__ void __launch_bounds__(256, 1) qkv_rope_kernel(
    const float* __restrict__ x,
    const float* __restrict__ wq,
    const float* __restrict__ wk,
    const float* __restrict__ wv,
    const float* __restrict__ R)
{
    extern __shared__ float sm[];
    float* xs   = sm;                   // [64][130]  x tile
    float* Ws   = xs + 64 * XS_ST;      // [128][130] weight matrix
    float* cso  = Ws + 128 * WS_ST;     // [64][65]   cos
    float* ssin = cso + 64 * CS_ST;     // [64][65]   sin

    const int tid   = threadIdx.x;
    const int b     = blockIdx.y;
    const int mbase = blockIdx.x * 64;

    // load x tile (coalesced float4)
    const float* xg = x + ((size_t)b * CW + mbase) * DIM;
    for (int idx = tid; idx < 64 * 32; idx += 256) {
        int r = idx >> 5, c4 = (idx & 31) * 4;
        float4 v = *reinterpret_cast<const float4*>(xg + r * DIM + c4);
        float* d = xs + r * XS_ST + c4;
        d[0] = v.x; d[1] = v.y; d[2] = v.z; d[3] = v.w;
    }
    // gather rotation coefficients from R's 2x2 block diagonal:
    //   c = R[m, 2i, 2i] ; s = R[m, 2i+1, 2i]
    for (int idx = tid; idx < 64 * 64; idx += 256) {
        int r = idx >> 6, i = idx & 63;
        const float* base = R + ((size_t)(mbase + r)) * (DIM * DIM) + i * 258;
        cso[r * CS_ST + i]  = base[0];
        ssin[r * CS_ST + i] = base[128];
    }

    const int ty = tid >> 4, tx = tid & 15;
    int woff[8];
    #pragma unroll
    for (int j = 0; j < 8; j++) {
        int p = j >> 1, u = j & 1;
        woff[j] = (2 * (tx + 16 * p) + u) * WS_ST;  // e = 2*(tx+16p)+u
    }

    for (int mat = 0; mat < 3; mat++) {
        __syncthreads();
        const float* w = (mat == 0) ? wq : (mat == 1) ? wk : wv;
        for (int idx = tid; idx < 128 * 32; idx += 256) {
            int e = idx >> 5, c4 = (idx & 31) * 4;
            float4 v = *reinterpret_cast<const float4*>(w + e * DIM + c4);
            float* d = Ws + e * WS_ST + c4;
            d[0] = v.x; d[1] = v.y; d[2] = v.z; d[3] = v.w;
        }
        __syncthreads();

        ull acc[4][8];
        #pragma unroll
        for (int i = 0; i < 4; i++)
            #pragma unroll
            for (int j = 0; j < 8; j++) acc[i][j] = 0ull;

        #pragma unroll 4
        for (int d2 = 0; d2 < 64; d2++) {
            ull a2[4];
            #pragma unroll
            for (int i = 0; i < 4; i++)
                a2[i] = ld2(xs + (4 * ty + i) * XS_ST + 2 * d2);
            #pragma unroll
            for (int j = 0; j < 8; j++) {
                ull b2 = ld2(Ws + woff[j] + 2 * d2);
                #pragma unroll
                for (int i = 0; i < 4; i++) ffma2(acc[i][j], a2[i], b2);
            }
        }

        float* dstg = ((mat == 0) ? g_q : (mat == 1) ? g_k : g_v)
                      + ((size_t)b * CW + mbase) * DIM;
        #pragma unroll
        for (int i = 0; i < 4; i++) {
            int r = 4 * ty + i;
            float val[8];
            #pragma unroll
            for (int j = 0; j < 8; j++) {
                float2 f = funpack2(acc[i][j]);
                val[j] = f.x + f.y;
            }
            #pragma unroll
            for (int p = 0; p < 4; p++) {
                int ep = tx + 16 * p;
                float o0, o1;
                if (mat < 2) {
                    float c = cso[r * CS_ST + ep], s = ssin[r * CS_ST + ep];
                    o0 =  val[2 * p] * c + val[2 * p + 1] * s;
                    o1 = -val[2 * p] * s + val[2 * p + 1] * c;
                } else {
                    o0 = val[2 * p]; o1 = val[2 * p + 1];
                }
                *reinterpret_cast<float2*>(dstg + r * DIM + 2 * ep) = make_float2(o0, o1);
            }
        }
    }
}

// ============================================================================
// Kernel B: causal flash attention, fp32 with packed f32x2 FFMA
//   BM=BN=64, D=128, 256 threads, 1 CTA per (batch, qtile); heavy tiles first
// ============================================================================
#define KST 130
#define SMEM_B ((4 * 64 * KST + 64 * 16 + 3 * 64) * 4)

__global__ void __launch_bounds__(256, 1) attn_kernel(float* __restrict__ out)
{
    extern __shared__ float sm[];
    float* Qs    = sm;                  // [64][130]
    float* Ks    = Qs + 64 * KST;       // [64][130]
    float* Vs    = Ks + 64 * KST;       // [64][130]
    float* P2    = Vs + 64 * KST;       // [64][130] : p stored duplicated (p,p)
    float* red   = P2 + 64 * KST;       // [64][16]
    float* sm_m  = red + 64 * 16;       // [64] running max
    float* sm_al = sm_m + 64;           // [64] alpha
    float* sm_l  = sm_al + 64;          // [64] running denom

    const int tid   = threadIdx.x;
    const int b     = blockIdx.y;
    const int qt    = 31 - (int)blockIdx.x;   // heavy tiles scheduled first
    const int qbase = qt * 64;
    const int ty    = tid >> 4, tx = tid & 15;

    if (tid < 64) { sm_m[tid] = -1e30f; sm_l[tid] = 0.0f; }

    const float* qg = g_q + ((size_t)b * CW + qbase) * DIM;
    for (int idx = tid; idx < 64 * 32; idx += 256) {
        int r = idx >> 5, c4 = (idx & 31) * 4;
        float4 v = *reinterpret_cast<const float4*>(qg + r * DIM + c4);
        float* d = Qs + r * KST + c4;
        d[0] = v.x; d[1] = v.y; d[2] = v.z; d[3] = v.w;
    }

    ull o2[4][4];   // rows 4ty+i ; dcols (2tx+32j, +1)
    #pragma unroll
    for (int i = 0; i < 4; i++)
        #pragma unroll
        for (int j = 0; j < 4; j++) o2[i][j] = 0ull;

    const float scale = 0.08838834764831845f;  // 1/sqrt(128)

    for (int kt = 0; kt <= qt; kt++) {
        const int kbase = kt * 64;
        __syncthreads();   // protect Ks/Vs from previous iteration's readers
        {
            const float* kg = g_k + ((size_t)b * CW + kbase) * DIM;
            const float* vg = g_v + ((size_t)b * CW + kbase) * DIM;
            for (int idx = tid; idx < 2 * 64 * 32; idx += 256) {
                int sel = idx >> 11;
                int id  = idx & 2047;
                int r = id >> 5, c4 = (id & 31) * 4;
                const float* src = sel ? vg : kg;
                float* dstb      = sel ? Vs : Ks;
                float4 v = *reinterpret_cast<const float4*>(src + r * DIM + c4);
                float* d = dstb + r * KST + c4;
                d[0] = v.x; d[1] = v.y; d[2] = v.z; d[3] = v.w;
            }
        }
        __syncthreads();

        // ---- S = Q K^T (f32x2 packed along d) ----
        ull acc[4][4];
        #pragma unroll
        for (int i = 0; i < 4; i++)
            #pragma unroll
            for (int j = 0; j < 4; j++) acc[i][j] = 0ull;

        #pragma unroll 4
        for (int d2 = 0; d2 < 64; d2++) {
            ull a2[4], b2[4];
            #pragma unroll
            for (int i = 0; i < 4; i++)
                a2[i] = ld2(Qs + (4 * ty + i) * KST + 2 * d2);
            #pragma unroll
            for (int j = 0; j < 4; j++)
                b2[j] = ld2(Ks + (tx + 16 * j) * KST + 2 * d2);
            #pragma unroll
            for (int i = 0; i < 4; i++)
                #pragma unroll
                for (int j = 0; j < 4; j++) ffma2(acc[i][j], a2[i], b2[j]);
        }

        float s[4][4];
        const bool diag = (kt == qt);
        #pragma unroll
        for (int i = 0; i < 4; i++)
            #pragma unroll
            for (int j = 0; j < 4; j++) {
                float2 f = funpack2(acc[i][j]);
                float v = (f.x + f.y) * scale;
                if (diag && (tx + 16 * j) > (4 * ty + i)) v = -1e30f;  // causal mask
                s[i][j] = v;
            }

        // ---- online softmax ----
        #pragma unroll
        for (int i = 0; i < 4; i++) {
            float pm = fmaxf(fmaxf(s[i][0], s[i][1]), fmaxf(s[i][2], s[i][3]));
            red[(4 * ty + i) * 16 + tx] = pm;
        }
        __syncthreads();
        if (tid < 64) {
            float mt = red[tid * 16];
            #pragma unroll
            for (int k = 1; k < 16; k++) mt = fmaxf(mt, red[tid * 16 + k]);
            float mo = sm_m[tid];
            float mn = fmaxf(mo, mt);
            sm_m[tid]  = mn;
            sm_al[tid] = __expf(mo - mn);
        }
        __syncthreads();
        #pragma unroll
        for (int i = 0; i < 4; i++) {
            int r = 4 * ty + i;
            float mr = sm_m[r];
            float al = sm_al[r];
            ull al2 = fpack2(al, al);
            #pragma unroll
            for (int j = 0; j < 4; j++) o2[i][j] = fmul2(o2[i][j], al2);
            float psum = 0.0f;
            #pragma unroll
            for (int j = 0; j < 4; j++) {
                float p = __expf(s[i][j] - mr);
                psum += p;
                st2(P2 + r * KST + 2 * (tx + 16 * j), fpack2(p, p));  // duplicated
            }
            red[r * 16 + tx] = psum;
        }
        __syncthreads();
        if (tid < 64) {
            float su = red[tid * 16];
            #pragma unroll
            for (int k = 1; k < 16; k++) su += red[tid * 16 + k];
            sm_l[tid] = sm_l[tid] * sm_al[tid] + su;
        }

        // ---- O += P V (f32x2 packed along dcol; P pre-duplicated) ----
        #pragma unroll 4
        for (int k = 0; k < 64; k++) {
            ull p2[4];
            #pragma unroll
            for (int i = 0; i < 4; i++)
                p2[i] = ld2(P2 + (4 * ty + i) * KST + 2 * k);
            #pragma unroll
            for (int j = 0; j < 4; j++) {
                ull v2 = ld2(Vs + k * KST + 2 * tx + 32 * j);
                #pragma unroll
                for (int i = 0; i < 4; i++) ffma2(o2[i][j], p2[i], v2);
            }
        }
    }

    __syncthreads();  // make final sm_l visible
    float* og = out + ((size_t)b * CW + qbase) * DIM;
    #pragma unroll
    for (int i = 0; i < 4; i++) {
        int r = 4 * ty + i;
        float linv = 1.0f / sm_l[r];
        ull l2 = fpack2(linv, linv);
        #pragma unroll
        for (int j = 0; j < 4; j++) {
            ull v = fmul2(o2[i][j], l2);
            st2(og + r * DIM + 2 * tx + 32 * j, v);
        }
    }
}

// ============================================================================
extern "C" void kernel_launch(void* const* d_in, const int* in_sizes, int n_in,
                              void* d_out, int out_size)
{
    (void)in_sizes; (void)n_in; (void)out_size;
    const float* x  = (const float*)d_in[0];
    const float* wq = (const float*)d_in[1];
    const float* wk = (const float*)d_in[2];
    const float* wv = (const float*)d_in[3];
    const float* R  = (const float*)d_in[4];
    float* out = (float*)d_out;

    cudaFuncSetAttribute(qkv_rope_kernel,
                         cudaFuncAttributeMaxDynamicSharedMemorySize, SMEM_A);
    cudaFuncSetAttribute(attn_kernel,
                         cudaFuncAttributeMaxDynamicSharedMemorySize, SMEM_B);

    qkv_rope_kernel<<<dim3(32, BATCH), 256, SMEM_A>>>(x, wq, wk, wv, R);
    attn_kernel<<<dim3(32, BATCH), 256, SMEM_B>>>(out);
}

// round 2
// speedup vs baseline: 1.5260x; 1.5260x over previous
#include <cuda_runtime.h>

#define CW 2048
#define DIM 128
#define BATCH 8

typedef unsigned long long ull;

// Scratch for projected+rotated Q/K and V (static __device__ per rules)
__device__ float g_q[BATCH * CW * DIM];
__device__ float g_k[BATCH * CW * DIM];
__device__ float g_v[BATCH * CW * DIM];

// ---------- packed fp32x2 helpers ----------
__device__ __forceinline__ ull ld2(const float* p) {
    return *reinterpret_cast<const ull*>(p);
}
__device__ __forceinline__ void st2(float* p, ull v) {
    *reinterpret_cast<ull*>(p) = v;
}
__device__ __forceinline__ void ffma2(ull& d, ull a, ull b) {
    asm("fma.rn.f32x2 %0, %1, %2, %0;" : "+l"(d) : "l"(a), "l"(b));
}
__device__ __forceinline__ ull fmul2(ull a, ull b) {
    ull r; asm("mul.rn.f32x2 %0, %1, %2;" : "=l"(r) : "l"(a), "l"(b)); return r;
}
__device__ __forceinline__ ull fpack2(float lo, float hi) {
    ull r; asm("mov.b64 %0, {%1, %2};" : "=l"(r) : "f"(lo), "f"(hi)); return r;
}
__device__ __forceinline__ float2 funpack2(ull v) {
    float lo, hi; asm("mov.b64 {%0, %1}, %2;" : "=f"(lo), "=f"(hi) : "l"(v));
    return make_float2(lo, hi);
}

// ---------- cp.async helpers ----------
__device__ __forceinline__ void cpa16(float* dst, const float* src) {
    unsigned s = (unsigned)__cvta_generic_to_shared(dst);
    asm volatile("cp.async.cg.shared.global [%0], [%1], 16;" :: "r"(s), "l"(src));
}
__device__ __forceinline__ void cpa_commit() {
    asm volatile("cp.async.commit_group;");
}
__device__ __forceinline__ void cpa_wait0() {
    asm volatile("cp.async.wait_group 0;");
}

// ---------- 16-lane shuffle reductions (rows live in half-warps) ----------
__device__ __forceinline__ float rmax16(float v) {
    #pragma unroll
    for (int off = 8; off; off >>= 1)
        v = fmaxf(v, __shfl_xor_sync(0xffffffffu, v, off, 16));
    return v;
}
__device__ __forceinline__ float rsum16(float v) {
    #pragma unroll
    for (int off = 8; off; off >>= 1)
        v += __shfl_xor_sync(0xffffffffu, v, off, 16);
    return v;
}

// ============================================================================
// Kernel A: fused QKV projection + RoPE (reads only the 2x2-block diag of R)
// ============================================================================
#define XS_ST 130
#define WS_ST 130
#define CS_ST 65
#define SMEM_A ((64 * XS_ST + 128 * WS_ST + 2 * 64 * CS_ST) * 4)

__global__ void __launch_bounds__(256, 1) qkv_rope_kernel(
    const float* __restrict__ x,
    const float* __restrict__ wq,
    const float* __restrict__ wk,
    const float* __restrict__ wv,
    const float* __restrict__ R)
{
    extern __shared__ float sm[];
    float* xs   = sm;                   // [64][130]
    float* Ws   = xs + 64 * XS_ST;      // [128][130]
    float* cso  = Ws + 128 * WS_ST;     // [64][65]
    float* ssin = cso + 64 * CS_ST;     // [64][65]

    const int tid   = threadIdx.x;
    const int b     = blockIdx.y;
    const int mbase = blockIdx.x * 64;

    const float* xg = x + ((size_t)b * CW + mbase) * DIM;
    for (int idx = tid; idx < 64 * 32; idx += 256) {
        int r = idx >> 5, c4 = (idx & 31) * 4;
        float4 v = *reinterpret_cast<const float4*>(xg + r * DIM + c4);
        float* d = xs + r * XS_ST + c4;
        d[0] = v.x; d[1] = v.y; d[2] = v.z; d[3] = v.w;
    }
    for (int idx = tid; idx < 64 * 64; idx += 256) {
        int r = idx >> 6, i = idx & 63;
        const float* base = R + ((size_t)(mbase + r)) * (DIM * DIM) + i * 258;
        cso[r * CS_ST + i]  = base[0];
        ssin[r * CS_ST + i] = base[128];
    }

    const int ty = tid >> 4, tx = tid & 15;
    int woff[8];
    #pragma unroll
    for (int j = 0; j < 8; j++) {
        int p = j >> 1, u = j & 1;
        woff[j] = (2 * (tx + 16 * p) + u) * WS_ST;
    }

    for (int mat = 0; mat < 3; mat++) {
        __syncthreads();
        const float* w = (mat == 0) ? wq : (mat == 1) ? wk : wv;
        for (int idx = tid; idx < 128 * 32; idx += 256) {
            int e = idx >> 5, c4 = (idx & 31) * 4;
            float4 v = *reinterpret_cast<const float4*>(w + e * DIM + c4);
            float* d = Ws + e * WS_ST + c4;
            d[0] = v.x; d[1] = v.y; d[2] = v.z; d[3] = v.w;
        }
        __syncthreads();

        ull acc[4][8];
        #pragma unroll
        for (int i = 0; i < 4; i++)
            #pragma unroll
            for (int j = 0; j < 8; j++) acc[i][j] = 0ull;

        #pragma unroll 4
        for (int d2 = 0; d2 < 64; d2++) {
            ull a2[4];
            #pragma unroll
            for (int i = 0; i < 4; i++)
                a2[i] = ld2(xs + (4 * ty + i) * XS_ST + 2 * d2);
            #pragma unroll
            for (int j = 0; j < 8; j++) {
                ull b2 = ld2(Ws + woff[j] + 2 * d2);
                #pragma unroll
                for (int i = 0; i < 4; i++) ffma2(acc[i][j], a2[i], b2);
            }
        }

        float* dstg = ((mat == 0) ? g_q : (mat == 1) ? g_k : g_v)
                      + ((size_t)b * CW + mbase) * DIM;
        #pragma unroll
        for (int i = 0; i < 4; i++) {
            int r = 4 * ty + i;
            float val[8];
            #pragma unroll
            for (int j = 0; j < 8; j++) {
                float2 f = funpack2(acc[i][j]);
                val[j] = f.x + f.y;
            }
            #pragma unroll
            for (int p = 0; p < 4; p++) {
                int ep = tx + 16 * p;
                float o0, o1;
                if (mat < 2) {
                    float c = cso[r * CS_ST + ep], s = ssin[r * CS_ST + ep];
                    o0 =  val[2 * p] * c + val[2 * p + 1] * s;
                    o1 = -val[2 * p] * s + val[2 * p + 1] * c;
                } else {
                    o0 = val[2 * p]; o1 = val[2 * p + 1];
                }
                *reinterpret_cast<float2*>(dstg + r * DIM + 2 * ep) = make_float2(o0, o1);
            }
        }
    }
}

// ============================================================================
// Kernel B: causal flash attention, fp32 f32x2 FFMA
//   BM=BN=64, 256 thr; cp.async double-buffered K/V; shuffle softmax;
//   LDS.128 operand loads; 2 barriers/iter.
// ============================================================================
#define ST 132
#define SMEM_B (6 * 64 * ST * 4)

__global__ void __launch_bounds__(256, 1) attn_kernel(float* __restrict__ out)
{
    extern __shared__ float sm[];
    float* Qs  = sm;                 // [64][132]
    float* Kb0 = sm + 1 * 64 * ST;
    float* Kb1 = sm + 2 * 64 * ST;
    float* Vb0 = sm + 3 * 64 * ST;
    float* Vb1 = sm + 4 * 64 * ST;
    float* P2  = sm + 5 * 64 * ST;   // p stored duplicated (p,p)

    const int tid = threadIdx.x;
    const int bid = blockIdx.x;
    const int b   = bid & 7;
    const int qt  = 31 - (bid >> 3);   // heavy tiles first (wave-1 = heaviest 148)
    const int qbase = qt * 64;
    const int ty = tid >> 4, tx = tid & 15;

    // async load Q tile + K/V tile 0
    {
        const float* qg = g_q + ((size_t)b * CW + qbase) * DIM;
        #pragma unroll
        for (int t = 0; t < 8; t++) {
            int idx = tid + t * 256;
            int r = idx >> 5, c4 = (idx & 31) * 4;
            cpa16(Qs + r * ST + c4, qg + r * DIM + c4);
        }
        const float* kg = g_k + ((size_t)b * CW) * DIM;
        const float* vg = g_v + ((size_t)b * CW) * DIM;
        #pragma unroll
        for (int t = 0; t < 8; t++) {
            int idx = tid + t * 256;
            int r = idx >> 5, c4 = (idx & 31) * 4;
            cpa16(Kb0 + r * ST + c4, kg + r * DIM + c4);
            cpa16(Vb0 + r * ST + c4, vg + r * DIM + c4);
        }
        cpa_commit();
    }

    ull o2[4][4];
    #pragma unroll
    for (int i = 0; i < 4; i++)
        #pragma unroll
        for (int j = 0; j < 4; j++) o2[i][j] = 0ull;
    float m_run[4], l_run[4];
    #pragma unroll
    for (int i = 0; i < 4; i++) { m_run[i] = -1e30f; l_run[i] = 0.0f; }

    const float scale = 0.08838834764831845f;  // 1/sqrt(128)

    cpa_wait0();
    __syncthreads();

    for (int kt = 0; kt <= qt; kt++) {
        const int cur = kt & 1;
        float* Kc = cur ? Kb1 : Kb0;
        float* Vc = cur ? Vb1 : Vb0;

        // prefetch kt+1 into the other buffer (safe: fully read in iter kt-1)
        if (kt < qt) {
            float* Kn = cur ? Kb0 : Kb1;
            float* Vn = cur ? Vb0 : Vb1;
            const float* kg = g_k + ((size_t)b * CW + (kt + 1) * 64) * DIM;
            const float* vg = g_v + ((size_t)b * CW + (kt + 1) * 64) * DIM;
            #pragma unroll
            for (int t = 0; t < 8; t++) {
                int idx = tid + t * 256;
                int r = idx >> 5, c4 = (idx & 31) * 4;
                cpa16(Kn + r * ST + c4, kg + r * DIM + c4);
                cpa16(Vn + r * ST + c4, vg + r * DIM + c4);
            }
        }
        cpa_commit();

        // ---- S = Q K^T (LDS.128 operands, f32x2 FFMA) ----
        ull acc[4][4];
        #pragma unroll
        for (int i = 0; i < 4; i++)
            #pragma unroll
            for (int j = 0; j < 4; j++) acc[i][j] = 0ull;

        #pragma unroll 2
        for (int d4 = 0; d4 < 32; d4++) {
            ulonglong2 a[4], bb[4];
            #pragma unroll
            for (int i = 0; i < 4; i++)
                a[i] = *reinterpret_cast<const ulonglong2*>(Qs + (4 * ty + i) * ST + 4 * d4);
            #pragma unroll
            for (int j = 0; j < 4; j++)
                bb[j] = *reinterpret_cast<const ulonglong2*>(Kc + (tx + 16 * j) * ST + 4 * d4);
            #pragma unroll
            for (int i = 0; i < 4; i++)
                #pragma unroll
                for (int j = 0; j < 4; j++) {
                    ffma2(acc[i][j], a[i].x, bb[j].x);
                    ffma2(acc[i][j], a[i].y, bb[j].y);
                }
        }

        float s[4][4];
        const bool diag = (kt == qt);
        #pragma unroll
        for (int i = 0; i < 4; i++)
            #pragma unroll
            for (int j = 0; j < 4; j++) {
                float2 f = funpack2(acc[i][j]);
                float v = (f.x + f.y) * scale;
                if (diag && (tx + 16 * j) > (4 * ty + i)) v = -1e30f;
                s[i][j] = v;
            }

        // ---- online softmax: register-resident, half-warp shuffles ----
        #pragma unroll
        for (int i = 0; i < 4; i++) {
            float pm = fmaxf(fmaxf(s[i][0], s[i][1]), fmaxf(s[i][2], s[i][3]));
            pm = rmax16(pm);
            float mo = m_run[i];
            float mn = fmaxf(mo, pm);
            float al = __expf(mo - mn);
            m_run[i] = mn;
            ull al2 = fpack2(al, al);
            #pragma unroll
            for (int j = 0; j < 4; j++) o2[i][j] = fmul2(o2[i][j], al2);
            float ps = 0.0f;
            #pragma unroll
            for (int j = 0; j < 4; j++) {
                float p = __expf(s[i][j] - mn);
                ps += p;
                st2(P2 + (4 * ty + i) * ST + 2 * (tx + 16 * j), fpack2(p, p));
            }
            ps = rsum16(ps);
            l_run[i] = l_run[i] * al + ps;
        }
        __syncthreads();   // P2 visible to all

        // ---- O += P V (P pre-duplicated; LDS.128 on P, LDS.64 on V) ----
        #pragma unroll 2
        for (int k2 = 0; k2 < 32; k2++) {
            ulonglong2 p[4];
            #pragma unroll
            for (int i = 0; i < 4; i++)
                p[i] = *reinterpret_cast<const ulonglong2*>(P2 + (4 * ty + i) * ST + 4 * k2);
            #pragma unroll
            for (int j = 0; j < 4; j++) {
                ull vlo = ld2(Vc + (2 * k2)     * ST + 2 * tx + 32 * j);
                ull vhi = ld2(Vc + (2 * k2 + 1) * ST + 2 * tx + 32 * j);
                #pragma unroll
                for (int i = 0; i < 4; i++) {
                    ffma2(o2[i][j], p[i].x, vlo);
                    ffma2(o2[i][j], p[i].y, vhi);
                }
            }
        }

        cpa_wait0();      // next K/V tile landed (hidden behind compute)
        __syncthreads();  // all PV reads of cur done; next tile visible
    }

    float* og = out + ((size_t)b * CW + qbase) * DIM;
    #pragma unroll
    for (int i = 0; i < 4; i++) {
        int r = 4 * ty + i;
        float linv = 1.0f / l_run[i];
        ull l2 = fpack2(linv, linv);
        #pragma unroll
        for (int j = 0; j < 4; j++)
            st2(og + r * DIM + 2 * tx + 32 * j, fmul2(o2[i][j], l2));
    }
}

// ============================================================================
extern "C" void kernel_launch(void* const* d_in, const int* in_sizes, int n_in,
                              void* d_out, int out_size)
{
    (void)in_sizes; (void)n_in; (void)out_size;
    const float* x  = (const float*)d_in[0];
    const float* wq = (const float*)d_in[1];
    const float* wk = (const float*)d_in[2];
    const float* wv = (const float*)d_in[3];
    const float* R  = (const float*)d_in[4];
    float* out = (float*)d_out;

    cudaFuncSetAttribute(qkv_rope_kernel,
                         cudaFuncAttributeMaxDynamicSharedMemorySize, SMEM_A);
    cudaFuncSetAttribute(attn_kernel,
                         cudaFuncAttributeMaxDynamicSharedMemorySize, SMEM_B);

    qkv_rope_kernel<<<dim3(32, BATCH), 256, SMEM_A>>>(x, wq, wk, wv, R);
    attn_kernel<<<256, 256, SMEM_B>>>(out);
}

// round 3
// speedup vs baseline: 1.5271x; 1.0007x over previous
#include <cuda_runtime.h>

#define CW 2048
#define DIM 128
#define BATCH 8

typedef unsigned long long ull;

// Scratch for projected+rotated Q/K and V (static __device__ per rules)
__device__ float g_q[BATCH * CW * DIM];
__device__ float g_k[BATCH * CW * DIM];
__device__ float g_v[BATCH * CW * DIM];

// ---------- packed fp32x2 helpers ----------
__device__ __forceinline__ ull ld2(const float* p) {
    return *reinterpret_cast<const ull*>(p);
}
__device__ __forceinline__ void st2(float* p, ull v) {
    *reinterpret_cast<ull*>(p) = v;
}
__device__ __forceinline__ void ffma2(ull& d, ull a, ull b) {
    asm("fma.rn.f32x2 %0, %1, %2, %0;" : "+l"(d) : "l"(a), "l"(b));
}
__device__ __forceinline__ ull fmul2(ull a, ull b) {
    ull r; asm("mul.rn.f32x2 %0, %1, %2;" : "=l"(r) : "l"(a), "l"(b)); return r;
}
__device__ __forceinline__ ull fpack2(float lo, float hi) {
    ull r; asm("mov.b64 %0, {%1, %2};" : "=l"(r) : "f"(lo), "f"(hi)); return r;
}
__device__ __forceinline__ float2 funpack2(ull v) {
    float lo, hi; asm("mov.b64 {%0, %1}, %2;" : "=f"(lo), "=f"(hi) : "l"(v));
    return make_float2(lo, hi);
}

// ---------- cp.async helpers ----------
__device__ __forceinline__ void cpa16(float* dst, const float* src) {
    unsigned s = (unsigned)__cvta_generic_to_shared(dst);
    asm volatile("cp.async.cg.shared.global [%0], [%1], 16;" :: "r"(s), "l"(src));
}
__device__ __forceinline__ void cpa_commit() {
    asm volatile("cp.async.commit_group;");
}
__device__ __forceinline__ void cpa_wait0() {
    asm volatile("cp.async.wait_group 0;");
}

// ---------- 16-lane shuffle reductions (rows live in half-warps) ----------
__device__ __forceinline__ float rmax16(float v) {
    #pragma unroll
    for (int off = 8; off; off >>= 1)
        v = fmaxf(v, __shfl_xor_sync(0xffffffffu, v, off, 16));
    return v;
}
__device__ __forceinline__ float rsum16(float v) {
    #pragma unroll
    for (int off = 8; off; off >>= 1)
        v += __shfl_xor_sync(0xffffffffu, v, off, 16);
    return v;
}

// ============================================================================
// Kernel A: fused QKV projection + RoPE (reads only the 2x2-block diag of R)
// ============================================================================
#define XS_ST 130
#define WS_ST 130
#define CS_ST 65
#define SMEM_A ((64 * XS_ST + 128 * WS_ST + 2 * 64 * CS_ST) * 4)

__global__ void __launch_bounds__(256, 1) qkv_rope_kernel(
    const float* __restrict__ x,
    const float* __restrict__ wq,
    const float* __restrict__ wk,
    const float* __restrict__ wv,
    const float* __restrict__ R)
{
    extern __shared__ float sm[];
    float* xs   = sm;                   // [64][130]
    float* Ws   = xs + 64 * XS_ST;      // [128][130]
    float* cso  = Ws + 128 * WS_ST;     // [64][65]
    float* ssin = cso + 64 * CS_ST;     // [64][65]

    const int tid   = threadIdx.x;
    const int b     = blockIdx.y;
    const int mbase = blockIdx.x * 64;

    const float* xg = x + ((size_t)b * CW + mbase) * DIM;
    for (int idx = tid; idx < 64 * 32; idx += 256) {
        int r = idx >> 5, c4 = (idx & 31) * 4;
        float4 v = *reinterpret_cast<const float4*>(xg + r * DIM + c4);
        float* d = xs + r * XS_ST + c4;
        d[0] = v.x; d[1] = v.y; d[2] = v.z; d[3] = v.w;
    }
    for (int idx = tid; idx < 64 * 64; idx += 256) {
        int r = idx >> 6, i = idx & 63;
        const float* base = R + ((size_t)(mbase + r)) * (DIM * DIM) + i * 258;
        cso[r * CS_ST + i]  = base[0];
        ssin[r * CS_ST + i] = base[128];
    }

    const int ty = tid >> 4, tx = tid & 15;
    int woff[8];
    #pragma unroll
    for (int j = 0; j < 8; j++) {
        int p = j >> 1, u = j & 1;
        woff[j] = (2 * (tx + 16 * p) + u) * WS_ST;
    }

    for (int mat = 0; mat < 3; mat++) {
        __syncthreads();
        const float* w = (mat == 0) ? wq : (mat == 1) ? wk : wv;
        for (int idx = tid; idx < 128 * 32; idx += 256) {
            int e = idx >> 5, c4 = (idx & 31) * 4;
            float4 v = *reinterpret_cast<const float4*>(w + e * DIM + c4);
            float* d = Ws + e * WS_ST + c4;
            d[0] = v.x; d[1] = v.y; d[2] = v.z; d[3] = v.w;
        }
        __syncthreads();

        ull acc[4][8];
        #pragma unroll
        for (int i = 0; i < 4; i++)
            #pragma unroll
            for (int j = 0; j < 8; j++) acc[i][j] = 0ull;

        #pragma unroll 4
        for (int d2 = 0; d2 < 64; d2++) {
            ull a2[4];
            #pragma unroll
            for (int i = 0; i < 4; i++)
                a2[i] = ld2(xs + (4 * ty + i) * XS_ST + 2 * d2);
            #pragma unroll
            for (int j = 0; j < 8; j++) {
                ull b2 = ld2(Ws + woff[j] + 2 * d2);
                #pragma unroll
                for (int i = 0; i < 4; i++) ffma2(acc[i][j], a2[i], b2);
            }
        }

        float* dstg = ((mat == 0) ? g_q : (mat == 1) ? g_k : g_v)
                      + ((size_t)b * CW + mbase) * DIM;
        #pragma unroll
        for (int i = 0; i < 4; i++) {
            int r = 4 * ty + i;
            float val[8];
            #pragma unroll
            for (int j = 0; j < 8; j++) {
                float2 f = funpack2(acc[i][j]);
                val[j] = f.x + f.y;
            }
            #pragma unroll
            for (int p = 0; p < 4; p++) {
                int ep = tx + 16 * p;
                float o0, o1;
                if (mat < 2) {
                    float c = cso[r * CS_ST + ep], s = ssin[r * CS_ST + ep];
                    o0 =  val[2 * p] * c + val[2 * p + 1] * s;
                    o1 = -val[2 * p] * s + val[2 * p + 1] * c;
                } else {
                    o0 = val[2 * p]; o1 = val[2 * p + 1];
                }
                *reinterpret_cast<float2*>(dstg + r * DIM + 2 * ep) = make_float2(o0, o1);
            }
        }
    }
}

// ============================================================================
// Kernel B: causal flash attention, fp32 f32x2 FFMA
//   BM=BN=64, 256 thr; cp.async double-buffered K/V; shuffle softmax;
//   LDS.128 operand loads; 2 barriers/iter.
// ============================================================================
#define ST 132
#define SMEM_B (6 * 64 * ST * 4)

__global__ void __launch_bounds__(256, 1) attn_kernel(float* __restrict__ out)
{
    extern __shared__ float sm[];
    float* Qs  = sm;                 // [64][132]
    float* Kb0 = sm + 1 * 64 * ST;
    float* Kb1 = sm + 2 * 64 * ST;
    float* Vb0 = sm + 3 * 64 * ST;
    float* Vb1 = sm + 4 * 64 * ST;
    float* P2  = sm + 5 * 64 * ST;   // p stored duplicated (p,p)

    const int tid = threadIdx.x;
    const int bid = blockIdx.x;
    const int b   = bid & 7;
    const int qt  = 31 - (bid >> 3);   // heavy tiles first (wave-1 = heaviest 148)
    const int qbase = qt * 64;
    const int ty = tid >> 4, tx = tid & 15;

    // async load Q tile + K/V tile 0
    {
        const float* qg = g_q + ((size_t)b * CW + qbase) * DIM;
        #pragma unroll
        for (int t = 0; t < 8; t++) {
            int idx = tid + t * 256;
            int r = idx >> 5, c4 = (idx & 31) * 4;
            cpa16(Qs + r * ST + c4, qg + r * DIM + c4);
        }
        const float* kg = g_k + ((size_t)b * CW) * DIM;
        const float* vg = g_v + ((size_t)b * CW) * DIM;
        #pragma unroll
        for (int t = 0; t < 8; t++) {
            int idx = tid + t * 256;
            int r = idx >> 5, c4 = (idx & 31) * 4;
            cpa16(Kb0 + r * ST + c4, kg + r * DIM + c4);
            cpa16(Vb0 + r * ST + c4, vg + r * DIM + c4);
        }
        cpa_commit();
    }

    ull o2[4][4];
    #pragma unroll
    for (int i = 0; i < 4; i++)
        #pragma unroll
        for (int j = 0; j < 4; j++) o2[i][j] = 0ull;
    float m_run[4], l_run[4];
    #pragma unroll
    for (int i = 0; i < 4; i++) { m_run[i] = -1e30f; l_run[i] = 0.0f; }

    const float scale = 0.08838834764831845f;  // 1/sqrt(128)

    cpa_wait0();
    __syncthreads();

    for (int kt = 0; kt <= qt; kt++) {
        const int cur = kt & 1;
        float* Kc = cur ? Kb1 : Kb0;
        float* Vc = cur ? Vb1 : Vb0;

        // prefetch kt+1 into the other buffer (safe: fully read in iter kt-1)
        if (kt < qt) {
            float* Kn = cur ? Kb0 : Kb1;
            float* Vn = cur ? Vb0 : Vb1;
            const float* kg = g_k + ((size_t)b * CW + (kt + 1) * 64) * DIM;
            const float* vg = g_v + ((size_t)b * CW + (kt + 1) * 64) * DIM;
            #pragma unroll
            for (int t = 0; t < 8; t++) {
                int idx = tid + t * 256;
                int r = idx >> 5, c4 = (idx & 31) * 4;
                cpa16(Kn + r * ST + c4, kg + r * DIM + c4);
                cpa16(Vn + r * ST + c4, vg + r * DIM + c4);
            }
        }
        cpa_commit();

        // ---- S = Q K^T (LDS.128 operands, f32x2 FFMA) ----
        ull acc[4][4];
        #pragma unroll
        for (int i = 0; i < 4; i++)
            #pragma unroll
            for (int j = 0; j < 4; j++) acc[i][j] = 0ull;

        #pragma unroll 2
        for (int d4 = 0; d4 < 32; d4++) {
            ulonglong2 a[4], bb[4];
            #pragma unroll
            for (int i = 0; i < 4; i++)
                a[i] = *reinterpret_cast<const ulonglong2*>(Qs + (4 * ty + i) * ST + 4 * d4);
            #pragma unroll
            for (int j = 0; j < 4; j++)
                bb[j] = *reinterpret_cast<const ulonglong2*>(Kc + (tx + 16 * j) * ST + 4 * d4);
            #pragma unroll
            for (int i = 0; i < 4; i++)
                #pragma unroll
                for (int j = 0; j < 4; j++) {
                    ffma2(acc[i][j], a[i].x, bb[j].x);
                    ffma2(acc[i][j], a[i].y, bb[j].y);
                }
        }

        float s[4][4];
        const bool diag = (kt == qt);
        #pragma unroll
        for (int i = 0; i < 4; i++)
            #pragma unroll
            for (int j = 0; j < 4; j++) {
                float2 f = funpack2(acc[i][j]);
                float v = (f.x + f.y) * scale;
                if (diag && (tx + 16 * j) > (4 * ty + i)) v = -1e30f;
                s[i][j] = v;
            }

        // ---- online softmax: register-resident, half-warp shuffles ----
        #pragma unroll
        for (int i = 0; i < 4; i++) {
            float pm = fmaxf(fmaxf(s[i][0], s[i][1]), fmaxf(s[i][2], s[i][3]));
            pm = rmax16(pm);
            float mo = m_run[i];
            float mn = fmaxf(mo, pm);
            float al = __expf(mo - mn);
            m_run[i] = mn;
            ull al2 = fpack2(al, al);
            #pragma unroll
            for (int j = 0; j < 4; j++) o2[i][j] = fmul2(o2[i][j], al2);
            float ps = 0.0f;
            #pragma unroll
            for (int j = 0; j < 4; j++) {
                float p = __expf(s[i][j] - mn);
                ps += p;
                st2(P2 + (4 * ty + i) * ST + 2 * (tx + 16 * j), fpack2(p, p));
            }
            ps = rsum16(ps);
            l_run[i] = l_run[i] * al + ps;
        }
        __syncthreads();   // P2 visible to all

        // ---- O += P V (P pre-duplicated; LDS.128 on P, LDS.64 on V) ----
        #pragma unroll 2
        for (int k2 = 0; k2 < 32; k2++) {
            ulonglong2 p[4];
            #pragma unroll
            for (int i = 0; i < 4; i++)
                p[i] = *reinterpret_cast<const ulonglong2*>(P2 + (4 * ty + i) * ST + 4 * k2);
            #pragma unroll
            for (int j = 0; j < 4; j++) {
                ull vlo = ld2(Vc + (2 * k2)     * ST + 2 * tx + 32 * j);
                ull vhi = ld2(Vc + (2 * k2 + 1) * ST + 2 * tx + 32 * j);
                #pragma unroll
                for (int i = 0; i < 4; i++) {
                    ffma2(o2[i][j], p[i].x, vlo);
                    ffma2(o2[i][j], p[i].y, vhi);
                }
            }
        }

        cpa_wait0();      // next K/V tile landed (hidden behind compute)
        __syncthreads();  // all PV reads of cur done; next tile visible
    }

    float* og = out + ((size_t)b * CW + qbase) * DIM;
    #pragma unroll
    for (int i = 0; i < 4; i++) {
        int r = 4 * ty + i;
        float linv = 1.0f / l_run[i];
        ull l2 = fpack2(linv, linv);
        #pragma unroll
        for (int j = 0; j < 4; j++)
            st2(og + r * DIM + 2 * tx + 32 * j, fmul2(o2[i][j], l2));
    }
}

// ============================================================================
extern "C" void kernel_launch(void* const* d_in, const int* in_sizes, int n_in,
                              void* d_out, int out_size)
{
    (void)in_sizes; (void)n_in; (void)out_size;
    const float* x  = (const float*)d_in[0];
    const float* wq = (const float*)d_in[1];
    const float* wk = (const float*)d_in[2];
    const float* wv = (const float*)d_in[3];
    const float* R  = (const float*)d_in[4];
    float* out = (float*)d_out;

    cudaFuncSetAttribute(qkv_rope_kernel,
                         cudaFuncAttributeMaxDynamicSharedMemorySize, SMEM_A);
    cudaFuncSetAttribute(attn_kernel,
                         cudaFuncAttributeMaxDynamicSharedMemorySize, SMEM_B);

    qkv_rope_kernel<<<dim3(32, BATCH), 256, SMEM_A>>>(x, wq, wk, wv, R);
    attn_kernel<<<256, 256, SMEM_B>>>(out);
}

// round 4
// speedup vs baseline: 1.5325x; 1.0035x over previous
#include <cuda_runtime.h>

#define CW 2048
#define DIM 128
#define BATCH 8

typedef unsigned long long ull;

// Scratch for projected+rotated Q/K and V (static __device__ per rules)
__device__ float g_q[BATCH * CW * DIM];
__device__ float g_k[BATCH * CW * DIM];
__device__ float g_v[BATCH * CW * DIM];

// ---------- packed fp32x2 helpers ----------
__device__ __forceinline__ ull ld2(const float* p) {
    return *reinterpret_cast<const ull*>(p);
}
__device__ __forceinline__ void st2(float* p, ull v) {
    *reinterpret_cast<ull*>(p) = v;
}
__device__ __forceinline__ void ffma2(ull& d, ull a, ull b) {
    asm("fma.rn.f32x2 %0, %1, %2, %0;" : "+l"(d) : "l"(a), "l"(b));
}
__device__ __forceinline__ ull fmul2(ull a, ull b) {
    ull r; asm("mul.rn.f32x2 %0, %1, %2;" : "=l"(r) : "l"(a), "l"(b)); return r;
}
__device__ __forceinline__ ull fpack2(float lo, float hi) {
    ull r; asm("mov.b64 %0, {%1, %2};" : "=l"(r) : "f"(lo), "f"(hi)); return r;
}
__device__ __forceinline__ float2 funpack2(ull v) {
    float lo, hi; asm("mov.b64 {%0, %1}, %2;" : "=f"(lo), "=f"(hi) : "l"(v));
    return make_float2(lo, hi);
}

// ---------- cp.async helpers ----------
__device__ __forceinline__ void cpa16(float* dst, const float* src) {
    unsigned s = (unsigned)__cvta_generic_to_shared(dst);
    asm volatile("cp.async.cg.shared.global [%0], [%1], 16;" :: "r"(s), "l"(src));
}
__device__ __forceinline__ void cpa_commit() {
    asm volatile("cp.async.commit_group;");
}
__device__ __forceinline__ void cpa_wait0() {
    asm volatile("cp.async.wait_group 0;");
}

// ---------- 16-lane shuffle reductions (rows live in half-warps) ----------
__device__ __forceinline__ float rmax16(float v) {
    #pragma unroll
    for (int off = 8; off; off >>= 1)
        v = fmaxf(v, __shfl_xor_sync(0xffffffffu, v, off, 16));
    return v;
}
__device__ __forceinline__ float rsum16(float v) {
    #pragma unroll
    for (int off = 8; off; off >>= 1)
        v += __shfl_xor_sync(0xffffffffu, v, off, 16);
    return v;
}

// ============================================================================
// Kernel A: fused QKV projection + RoPE (reads only the 2x2-block diag of R)
// ============================================================================
#define XS_ST 130
#define WS_ST 130
#define CS_ST 65
#define SMEM_A ((64 * XS_ST + 128 * WS_ST + 2 * 64 * CS_ST) * 4)

__global__ void __launch_bounds__(256, 1) qkv_rope_kernel(
    const float* __restrict__ x,
    const float* __restrict__ wq,
    const float* __restrict__ wk,
    const float* __restrict__ wv,
    const float* __restrict__ R)
{
    extern __shared__ float sm[];
    float* xs   = sm;                   // [64][130]
    float* Ws   = xs + 64 * XS_ST;      // [128][130]
    float* cso  = Ws + 128 * WS_ST;     // [64][65]
    float* ssin = cso + 64 * CS_ST;     // [64][65]

    const int tid   = threadIdx.x;
    const int b     = blockIdx.y;
    const int mbase = blockIdx.x * 64;

    const float* xg = x + ((size_t)b * CW + mbase) * DIM;
    for (int idx = tid; idx < 64 * 32; idx += 256) {
        int r = idx >> 5, c4 = (idx & 31) * 4;
        float4 v = *reinterpret_cast<const float4*>(xg + r * DIM + c4);
        float* d = xs + r * XS_ST + c4;
        d[0] = v.x; d[1] = v.y; d[2] = v.z; d[3] = v.w;
    }
    for (int idx = tid; idx < 64 * 64; idx += 256) {
        int r = idx >> 6, i = idx & 63;
        const float* base = R + ((size_t)(mbase + r)) * (DIM * DIM) + i * 258;
        cso[r * CS_ST + i]  = base[0];
        ssin[r * CS_ST + i] = base[128];
    }

    const int ty = tid >> 4, tx = tid & 15;
    int woff[8];
    #pragma unroll
    for (int j = 0; j < 8; j++) {
        int p = j >> 1, u = j & 1;
        woff[j] = (2 * (tx + 16 * p) + u) * WS_ST;
    }

    for (int mat = 0; mat < 3; mat++) {
        __syncthreads();
        const float* w = (mat == 0) ? wq : (mat == 1) ? wk : wv;
        for (int idx = tid; idx < 128 * 32; idx += 256) {
            int e = idx >> 5, c4 = (idx & 31) * 4;
            float4 v = *reinterpret_cast<const float4*>(w + e * DIM + c4);
            float* d = Ws + e * WS_ST + c4;
            d[0] = v.x; d[1] = v.y; d[2] = v.z; d[3] = v.w;
        }
        __syncthreads();

        ull acc[4][8];
        #pragma unroll
        for (int i = 0; i < 4; i++)
            #pragma unroll
            for (int j = 0; j < 8; j++) acc[i][j] = 0ull;

        #pragma unroll 4
        for (int d2 = 0; d2 < 64; d2++) {
            ull a2[4];
            #pragma unroll
            for (int i = 0; i < 4; i++)
                a2[i] = ld2(xs + (4 * ty + i) * XS_ST + 2 * d2);
            #pragma unroll
            for (int j = 0; j < 8; j++) {
                ull b2 = ld2(Ws + woff[j] + 2 * d2);
                #pragma unroll
                for (int i = 0; i < 4; i++) ffma2(acc[i][j], a2[i], b2);
            }
        }

        float* dstg = ((mat == 0) ? g_q : (mat == 1) ? g_k : g_v)
                      + ((size_t)b * CW + mbase) * DIM;
        #pragma unroll
        for (int i = 0; i < 4; i++) {
            int r = 4 * ty + i;
            float val[8];
            #pragma unroll
            for (int j = 0; j < 8; j++) {
                float2 f = funpack2(acc[i][j]);
                val[j] = f.x + f.y;
            }
            #pragma unroll
            for (int p = 0; p < 4; p++) {
                int ep = tx + 16 * p;
                float o0, o1;
                if (mat < 2) {
                    float c = cso[r * CS_ST + ep], s = ssin[r * CS_ST + ep];
                    o0 =  val[2 * p] * c + val[2 * p + 1] * s;
                    o1 = -val[2 * p] * s + val[2 * p + 1] * c;
                } else {
                    o0 = val[2 * p]; o1 = val[2 * p + 1];
                }
                *reinterpret_cast<float2*>(dstg + r * DIM + 2 * ep) = make_float2(o0, o1);
            }
        }
    }
}

// ============================================================================
// Kernel B: causal flash attention, fp32 f32x2 FFMA
//   BM=BN=64, 256 thr; cp.async double-buffered K/V; shuffle softmax;
//   LDS.128 operand loads; 2 barriers/iter.
// ============================================================================
#define ST 132
#define SMEM_B (6 * 64 * ST * 4)

__global__ void __launch_bounds__(256, 1) attn_kernel(float* __restrict__ out)
{
    extern __shared__ float sm[];
    float* Qs  = sm;                 // [64][132]
    float* Kb0 = sm + 1 * 64 * ST;
    float* Kb1 = sm + 2 * 64 * ST;
    float* Vb0 = sm + 3 * 64 * ST;
    float* Vb1 = sm + 4 * 64 * ST;
    float* P2  = sm + 5 * 64 * ST;   // p stored duplicated (p,p)

    const int tid = threadIdx.x;
    const int bid = blockIdx.x;
    const int b   = bid & 7;
    const int qt  = 31 - (bid >> 3);   // heavy tiles first (wave-1 = heaviest 148)
    const int qbase = qt * 64;
    const int ty = tid >> 4, tx = tid & 15;

    // async load Q tile + K/V tile 0
    {
        const float* qg = g_q + ((size_t)b * CW + qbase) * DIM;
        #pragma unroll
        for (int t = 0; t < 8; t++) {
            int idx = tid + t * 256;
            int r = idx >> 5, c4 = (idx & 31) * 4;
            cpa16(Qs + r * ST + c4, qg + r * DIM + c4);
        }
        const float* kg = g_k + ((size_t)b * CW) * DIM;
        const float* vg = g_v + ((size_t)b * CW) * DIM;
        #pragma unroll
        for (int t = 0; t < 8; t++) {
            int idx = tid + t * 256;
            int r = idx >> 5, c4 = (idx & 31) * 4;
            cpa16(Kb0 + r * ST + c4, kg + r * DIM + c4);
            cpa16(Vb0 + r * ST + c4, vg + r * DIM + c4);
        }
        cpa_commit();
    }

    ull o2[4][4];
    #pragma unroll
    for (int i = 0; i < 4; i++)
        #pragma unroll
        for (int j = 0; j < 4; j++) o2[i][j] = 0ull;
    float m_run[4], l_run[4];
    #pragma unroll
    for (int i = 0; i < 4; i++) { m_run[i] = -1e30f; l_run[i] = 0.0f; }

    const float scale = 0.08838834764831845f;  // 1/sqrt(128)

    cpa_wait0();
    __syncthreads();

    for (int kt = 0; kt <= qt; kt++) {
        const int cur = kt & 1;
        float* Kc = cur ? Kb1 : Kb0;
        float* Vc = cur ? Vb1 : Vb0;

        // prefetch kt+1 into the other buffer (safe: fully read in iter kt-1)
        if (kt < qt) {
            float* Kn = cur ? Kb0 : Kb1;
            float* Vn = cur ? Vb0 : Vb1;
            const float* kg = g_k + ((size_t)b * CW + (kt + 1) * 64) * DIM;
            const float* vg = g_v + ((size_t)b * CW + (kt + 1) * 64) * DIM;
            #pragma unroll
            for (int t = 0; t < 8; t++) {
                int idx = tid + t * 256;
                int r = idx >> 5, c4 = (idx & 31) * 4;
                cpa16(Kn + r * ST + c4, kg + r * DIM + c4);
                cpa16(Vn + r * ST + c4, vg + r * DIM + c4);
            }
        }
        cpa_commit();

        // ---- S = Q K^T (LDS.128 operands, f32x2 FFMA) ----
        ull acc[4][4];
        #pragma unroll
        for (int i = 0; i < 4; i++)
            #pragma unroll
            for (int j = 0; j < 4; j++) acc[i][j] = 0ull;

        #pragma unroll 2
        for (int d4 = 0; d4 < 32; d4++) {
            ulonglong2 a[4], bb[4];
            #pragma unroll
            for (int i = 0; i < 4; i++)
                a[i] = *reinterpret_cast<const ulonglong2*>(Qs + (4 * ty + i) * ST + 4 * d4);
            #pragma unroll
            for (int j = 0; j < 4; j++)
                bb[j] = *reinterpret_cast<const ulonglong2*>(Kc + (tx + 16 * j) * ST + 4 * d4);
            #pragma unroll
            for (int i = 0; i < 4; i++)
                #pragma unroll
                for (int j = 0; j < 4; j++) {
                    ffma2(acc[i][j], a[i].x, bb[j].x);
                    ffma2(acc[i][j], a[i].y, bb[j].y);
                }
        }

        float s[4][4];
        const bool diag = (kt == qt);
        #pragma unroll
        for (int i = 0; i < 4; i++)
            #pragma unroll
            for (int j = 0; j < 4; j++) {
                float2 f = funpack2(acc[i][j]);
                float v = (f.x + f.y) * scale;
                if (diag && (tx + 16 * j) > (4 * ty + i)) v = -1e30f;
                s[i][j] = v;
            }

        // ---- online softmax: register-resident, half-warp shuffles ----
        #pragma unroll
        for (int i = 0; i < 4; i++) {
            float pm = fmaxf(fmaxf(s[i][0], s[i][1]), fmaxf(s[i][2], s[i][3]));
            pm = rmax16(pm);
            float mo = m_run[i];
            float mn = fmaxf(mo, pm);
            float al = __expf(mo - mn);
            m_run[i] = mn;
            ull al2 = fpack2(al, al);
            #pragma unroll
            for (int j = 0; j < 4; j++) o2[i][j] = fmul2(o2[i][j], al2);
            float ps = 0.0f;
            #pragma unroll
            for (int j = 0; j < 4; j++) {
                float p = __expf(s[i][j] - mn);
                ps += p;
                st2(P2 + (4 * ty + i) * ST + 2 * (tx + 16 * j), fpack2(p, p));
            }
            ps = rsum16(ps);
            l_run[i] = l_run[i] * al + ps;
        }
        __syncthreads();   // P2 visible to all

        // ---- O += P V (P pre-duplicated; LDS.128 on P, LDS.64 on V) ----
        #pragma unroll 2
        for (int k2 = 0; k2 < 32; k2++) {
            ulonglong2 p[4];
            #pragma unroll
            for (int i = 0; i < 4; i++)
                p[i] = *reinterpret_cast<const ulonglong2*>(P2 + (4 * ty + i) * ST + 4 * k2);
            #pragma unroll
            for (int j = 0; j < 4; j++) {
                ull vlo = ld2(Vc + (2 * k2)     * ST + 2 * tx + 32 * j);
                ull vhi = ld2(Vc + (2 * k2 + 1) * ST + 2 * tx + 32 * j);
                #pragma unroll
                for (int i = 0; i < 4; i++) {
                    ffma2(o2[i][j], p[i].x, vlo);
                    ffma2(o2[i][j], p[i].y, vhi);
                }
            }
        }

        cpa_wait0();      // next K/V tile landed (hidden behind compute)
        __syncthreads();  // all PV reads of cur done; next tile visible
    }

    float* og = out + ((size_t)b * CW + qbase) * DIM;
    #pragma unroll
    for (int i = 0; i < 4; i++) {
        int r = 4 * ty + i;
        float linv = 1.0f / l_run[i];
        ull l2 = fpack2(linv, linv);
        #pragma unroll
        for (int j = 0; j < 4; j++)
            st2(og + r * DIM + 2 * tx + 32 * j, fmul2(o2[i][j], l2));
    }
}

// ============================================================================
extern "C" void kernel_launch(void* const* d_in, const int* in_sizes, int n_in,
                              void* d_out, int out_size)
{
    (void)in_sizes; (void)n_in; (void)out_size;
    const float* x  = (const float*)d_in[0];
    const float* wq = (const float*)d_in[1];
    const float* wk = (const float*)d_in[2];
    const float* wv = (const float*)d_in[3];
    const float* R  = (const float*)d_in[4];
    float* out = (float*)d_out;

    cudaFuncSetAttribute(qkv_rope_kernel,
                         cudaFuncAttributeMaxDynamicSharedMemorySize, SMEM_A);
    cudaFuncSetAttribute(attn_kernel,
                         cudaFuncAttributeMaxDynamicSharedMemorySize, SMEM_B);

    qkv_rope_kernel<<<dim3(32, BATCH), 256, SMEM_A>>>(x, wq, wk, wv, R);
    attn_kernel<<<256, 256, SMEM_B>>>(out);
}

// round 7
// speedup vs baseline: 2.1694x; 1.4156x over previous
#include <cuda_runtime.h>
#include <cuda_bf16.h>
#include <cstdint>

#define CW 2048
#define DIM 128
#define BATCH 8
typedef unsigned long long ull;

__device__ __nv_bfloat16 g_qh[BATCH*CW*DIM], g_ql[BATCH*CW*DIM];
__device__ __nv_bfloat16 g_kh[BATCH*CW*DIM], g_kl[BATCH*CW*DIM];
__device__ __nv_bfloat16 g_vth[BATCH*DIM*CW], g_vtl[BATCH*DIM*CW];

// ---- helpers ----
__device__ __forceinline__ ull ld2(const float* p){ return *reinterpret_cast<const ull*>(p); }
__device__ __forceinline__ void ffma2(ull& d, ull a, ull b){
    asm("fma.rn.f32x2 %0, %1, %2, %0;" : "+l"(d) : "l"(a), "l"(b));
}
__device__ __forceinline__ float2 funpack2(ull v){
    float lo,hi; asm("mov.b64 {%0,%1}, %2;" : "=f"(lo),"=f"(hi) : "l"(v)); return make_float2(lo,hi);
}
__device__ __forceinline__ uint32_t bf2pack(float lo, float hi){   // low half <- lo
    uint32_t r; asm("cvt.rn.bf16x2.f32 %0, %1, %2;" : "=r"(r) : "f"(hi), "f"(lo)); return r;
}
__device__ __forceinline__ void cpa16s(uint32_t dst, const void* src){
    asm volatile("cp.async.cg.shared.global [%0], [%1], 16;" :: "r"(dst), "l"(src));
}
__device__ __forceinline__ void ldsm4(uint32_t* r, uint32_t a){
    asm volatile("ldmatrix.sync.aligned.m8n8.x4.shared.b16 {%0,%1,%2,%3}, [%4];"
        : "=r"(r[0]),"=r"(r[1]),"=r"(r[2]),"=r"(r[3]) : "r"(a));
}
__device__ __forceinline__ void mma_bf16(float* c, const uint32_t* a, const uint32_t* b){
    asm volatile("mma.sync.aligned.m16n8k16.row.col.f32.bf16.bf16.f32 "
        "{%0,%1,%2,%3}, {%4,%5,%6,%7}, {%8,%9}, {%0,%1,%2,%3};"
        : "+f"(c[0]),"+f"(c[1]),"+f"(c[2]),"+f"(c[3])
        : "r"(a[0]),"r"(a[1]),"r"(a[2]),"r"(a[3]),"r"(b[0]),"r"(b[1]));
}

// ============================================================================
// Kernel A: QKV projection + RoPE -> Q/K bf16 hi/lo row-major, V^T bf16 hi/lo
// ============================================================================
#define XS_ST 130
#define WS_ST 130
#define CS_ST 65
#define SMEM_A ((64*XS_ST + 128*WS_ST + 2*64*CS_ST)*4)

__global__ void __launch_bounds__(256,1) qkv_rope_kernel(
    const float* __restrict__ x, const float* __restrict__ wq,
    const float* __restrict__ wk, const float* __restrict__ wv,
    const float* __restrict__ R)
{
    extern __shared__ float sm[];
    float* xs = sm;
    float* Ws = xs + 64*XS_ST;
    float* cso = Ws + 128*WS_ST;
    float* ssin = cso + 64*CS_ST;
    const int tid = threadIdx.x, b = blockIdx.y, mbase = blockIdx.x*64;

    const float* xg = x + ((size_t)b*CW + mbase)*DIM;
    for (int idx = tid; idx < 64*32; idx += 256){
        int r = idx>>5, c4 = (idx&31)*4;
        float4 v = *reinterpret_cast<const float4*>(xg + r*DIM + c4);
        float* d = xs + r*XS_ST + c4;
        d[0]=v.x; d[1]=v.y; d[2]=v.z; d[3]=v.w;
    }
    for (int idx = tid; idx < 64*64; idx += 256){
        int r = idx>>6, i = idx&63;
        const float* base = R + ((size_t)(mbase+r))*(DIM*DIM) + i*258;
        cso[r*CS_ST+i] = base[0]; ssin[r*CS_ST+i] = base[128];
    }
    const int ty = tid>>4, tx = tid&15;
    int woff[8];
    #pragma unroll
    for (int j = 0; j < 8; j++){ int p = j>>1, u = j&1; woff[j] = (2*(tx+16*p)+u)*WS_ST; }

    for (int mat = 0; mat < 3; mat++){
        __syncthreads();
        const float* w = (mat==0)?wq:(mat==1)?wk:wv;
        for (int idx = tid; idx < 128*32; idx += 256){
            int e = idx>>5, c4 = (idx&31)*4;
            float4 v = *reinterpret_cast<const float4*>(w + e*DIM + c4);
            float* d = Ws + e*WS_ST + c4;
            d[0]=v.x; d[1]=v.y; d[2]=v.z; d[3]=v.w;
        }
        __syncthreads();

        ull acc[4][8];
        #pragma unroll
        for (int i = 0; i < 4; i++){
            #pragma unroll
            for (int j = 0; j < 8; j++) acc[i][j] = 0ull;
        }
        #pragma unroll 4
        for (int d2 = 0; d2 < 64; d2++){
            ull a2[4];
            #pragma unroll
            for (int i = 0; i < 4; i++) a2[i] = ld2(xs + (4*ty+i)*XS_ST + 2*d2);
            #pragma unroll
            for (int j = 0; j < 8; j++){
                ull b2 = ld2(Ws + woff[j] + 2*d2);
                #pragma unroll
                for (int i = 0; i < 4; i++) ffma2(acc[i][j], a2[i], b2);
            }
        }
        float val[4][8];
        #pragma unroll
        for (int i = 0; i < 4; i++){
            #pragma unroll
            for (int j = 0; j < 8; j++){ float2 f = funpack2(acc[i][j]); val[i][j] = f.x + f.y; }
        }

        if (mat < 2){
            uint32_t* gh = reinterpret_cast<uint32_t*>(mat==0 ? g_qh : g_kh);
            uint32_t* gl = reinterpret_cast<uint32_t*>(mat==0 ? g_ql : g_kl);
            #pragma unroll
            for (int i = 0; i < 4; i++){
                int r = 4*ty+i;
                size_t rowp = ((size_t)b*CW + mbase + r)*64;
                #pragma unroll
                for (int p = 0; p < 4; p++){
                    int ep = tx + 16*p;
                    float c = cso[r*CS_ST+ep], s = ssin[r*CS_ST+ep];
                    float o0 =  val[i][2*p]*c + val[i][2*p+1]*s;
                    float o1 = -val[i][2*p]*s + val[i][2*p+1]*c;
                    uint32_t h = bf2pack(o0, o1);
                    float h0 = __uint_as_float(h<<16), h1 = __uint_as_float(h & 0xFFFF0000u);
                    gh[rowp+ep] = h;
                    gl[rowp+ep] = bf2pack(o0-h0, o1-h1);
                }
            }
        } else {
            __syncthreads();
            unsigned short* vth_s = reinterpret_cast<unsigned short*>(Ws);
            unsigned short* vtl_s = vth_s + 128*66;
            #pragma unroll
            for (int i = 0; i < 4; i++){
                int r = 4*ty+i;
                #pragma unroll
                for (int p = 0; p < 4; p++){
                    int ep = tx + 16*p;
                    float o0 = val[i][2*p], o1 = val[i][2*p+1];
                    uint32_t h = bf2pack(o0, o1);
                    float h0 = __uint_as_float(h<<16), h1 = __uint_as_float(h & 0xFFFF0000u);
                    uint32_t l = bf2pack(o0-h0, o1-h1);
                    vth_s[(2*ep)  *66 + r] = (unsigned short)(h & 0xFFFF);
                    vth_s[(2*ep+1)*66 + r] = (unsigned short)(h >> 16);
                    vtl_s[(2*ep)  *66 + r] = (unsigned short)(l & 0xFFFF);
                    vtl_s[(2*ep+1)*66 + r] = (unsigned short)(l >> 16);
                }
            }
            __syncthreads();
            uint32_t* gh = reinterpret_cast<uint32_t*>(g_vth);
            uint32_t* gl = reinterpret_cast<uint32_t*>(g_vtl);
            for (int idx = tid; idx < 128*32; idx += 256){
                int d = idx>>5, mp = idx&31;
                size_t dst = ((size_t)(b*DIM + d)*CW + mbase)/2 + mp;
                gh[dst] = *reinterpret_cast<uint32_t*>(&vth_s[d*66 + 2*mp]);
                gl[dst] = *reinterpret_cast<uint32_t*>(&vtl_s[d*66 + 2*mp]);
            }
        }
    }
}

// ============================================================================
// Kernel B: HMMA (mma.sync bf16) flash attention, bf16x3, unnormalized softmax
//   BM=128, BN=64, 8 warps; Q and P as register fragments; K/V^T dbl-buffered
// ============================================================================
#define STK 272
#define STV 144
#define KBYTES (64*STK)                  // 17408
#define VBYTES (128*STV)                 // 18432
#define BUF (2*KBYTES + 2*VBYTES)        // 71680
#define SMEM_BB (2*BUF)                  // 143360

__device__ __forceinline__ void load_kv_stage(uint32_t sb, int b, int kt, int buf, int tid){
    const char* kh = (const char*)(g_kh  + ((size_t)b*CW + kt*64)*DIM);
    const char* kl = (const char*)(g_kl  + ((size_t)b*CW + kt*64)*DIM);
    const char* vh = (const char*)(g_vth + (size_t)b*DIM*CW + kt*64);
    const char* vl = (const char*)(g_vtl + (size_t)b*DIM*CW + kt*64);
    uint32_t bo = sb + buf*BUF;
    #pragma unroll
    for (int t = 0; t < 4; t++){
        int c = tid + t*256;                       // K: 64 rows x 16 chunks
        int n = c>>4, cb = (c&15)*16;
        uint32_t dst = bo + n*STK + cb;
        cpa16s(dst,          kh + n*256 + cb);
        cpa16s(dst + KBYTES, kl + n*256 + cb);
    }
    #pragma unroll
    for (int t = 0; t < 4; t++){
        int c = tid + t*256;                       // V^T: 128 rows x 8 chunks
        int d = c>>3, cb = (c&7)*16;
        uint32_t dst = bo + 2*KBYTES + d*STV + cb;
        cpa16s(dst,          vh + (size_t)d*CW*2 + cb);
        cpa16s(dst + VBYTES, vl + (size_t)d*CW*2 + cb);
    }
}

__global__ void __launch_bounds__(256,1) attn_hmma_kernel(float* __restrict__ out)
{
    extern __shared__ char smc[];
    const uint32_t sb = (uint32_t)__cvta_generic_to_shared(smc);
    const int tid = threadIdx.x, w = tid>>5, lane = tid&31;
    const int b = blockIdx.x & 7;
    const int qt = 15 - ((int)blockIdx.x >> 3);    // heavy q-tiles first
    const int qbase = qt*128;
    const int ktmax = 2*qt + 1;
    const int l7 = lane & 7, lhi = lane >> 3;
    const int lg = lane >> 2, lt = lane & 3;

    // ---- prologue: stage Q (in buf1 area), K/V tile0 (buf0) ----
    {
        const char* qh = (const char*)(g_qh + ((size_t)b*CW + qbase)*DIM);
        const char* ql = (const char*)(g_ql + ((size_t)b*CW + qbase)*DIM);
        #pragma unroll
        for (int t = 0; t < 8; t++){
            int c = tid + t*256;                   // 128 rows x 16 chunks
            int n = c>>4, cb = (c&15)*16;
            uint32_t dst = sb + BUF + n*STK + cb;
            cpa16s(dst,         qh + n*256 + cb);
            cpa16s(dst + 34816, ql + n*256 + cb);
        }
        asm volatile("cp.async.commit_group;");    // G0: Q
        load_kv_stage(sb, b, 0, 0, tid);
        asm volatile("cp.async.commit_group;");    // G1: tile0
    }
    asm volatile("cp.async.wait_group 1;");        // Q landed
    __syncthreads();

    // Q A-fragments (8 k-chunks, hi+lo)
    uint32_t qh[8][4], ql[8][4];
    {
        uint32_t qa = sb + BUF + (16*w + (lane&15))*STK + (lane>>4)*16;
        #pragma unroll
        for (int c = 0; c < 8; c++){
            ldsm4(qh[c], qa + c*32);
            ldsm4(ql[c], qa + 34816 + c*32);
        }
    }

    float o[16][4];
    #pragma unroll
    for (int jd = 0; jd < 16; jd++){
        #pragma unroll
        for (int i = 0; i < 4; i++) o[jd][i] = 0.0f;
    }
    float lsum0 = 0.0f, lsum1 = 0.0f;
    const float sc = 0.08838834764831845f;         // 1/sqrt(128)
    const int rg0 = qbase + 16*w + lg;             // row of c0/c1 (c2/c3: +8)

    for (int kt = 0; kt <= ktmax; kt++){
        __syncthreads();                            // prior reads of buf[(kt+1)&1] done
        if (kt < ktmax) load_kv_stage(sb, b, kt+1, (kt+1)&1, tid);
        asm volatile("cp.async.commit_group;");
        asm volatile("cp.async.wait_group 1;");     // stage kt landed
        __syncthreads();

        const uint32_t bo = sb + (kt&1)*BUF;
        const uint32_t khs = bo, kls = bo + KBYTES;
        const uint32_t vhs = bo + 2*KBYTES, vls = vhs + VBYTES;

        // ---- S = Q K^T : per n-tile j (8 cols), 24 HMMA ----
        float s[8][4];
        #pragma unroll
        for (int j = 0; j < 8; j++){
            s[j][0]=s[j][1]=s[j][2]=s[j][3]=0.0f;
            uint32_t ka = khs + (8*j + l7)*STK + lhi*16;
            uint32_t la = kls + (8*j + l7)*STK + lhi*16;
            uint32_t bh[8][2], bl[8][2];
            #pragma unroll
            for (int c2 = 0; c2 < 4; c2++){
                uint32_t t4[4];
                ldsm4(t4, ka + c2*64);
                bh[2*c2][0]=t4[0]; bh[2*c2][1]=t4[1]; bh[2*c2+1][0]=t4[2]; bh[2*c2+1][1]=t4[3];
                ldsm4(t4, la + c2*64);
                bl[2*c2][0]=t4[0]; bl[2*c2][1]=t4[1]; bl[2*c2+1][0]=t4[2]; bl[2*c2+1][1]=t4[3];
            }
            #pragma unroll
            for (int ch = 0; ch < 8; ch++){
                mma_bf16(s[j], qh[ch], bh[ch]);
                mma_bf16(s[j], qh[ch], bl[ch]);
                mma_bf16(s[j], ql[ch], bh[ch]);
            }
        }

        // ---- softmax (unnormalized) + repack S-acc -> P A-fragments ----
        const bool domask = (kt >= 2*qt);
        uint32_t ph[4][4], pl[4][4];
        #pragma unroll
        for (int j = 0; j < 8; j++){
            int cg = kt*64 + 8*j + 2*lt;
            float p0 = __expf(s[j][0]*sc);
            float p1 = __expf(s[j][1]*sc);
            float p2 = __expf(s[j][2]*sc);
            float p3 = __expf(s[j][3]*sc);
            if (domask){
                if (cg   > rg0)     p0 = 0.0f;
                if (cg+1 > rg0)     p1 = 0.0f;
                if (cg   > rg0+8)   p2 = 0.0f;
                if (cg+1 > rg0+8)   p3 = 0.0f;
            }
            lsum0 += p0 + p1;
            lsum1 += p2 + p3;
            uint32_t h01 = bf2pack(p0, p1), h23 = bf2pack(p2, p3);
            float h0 = __uint_as_float(h01<<16), h1 = __uint_as_float(h01 & 0xFFFF0000u);
            float h2 = __uint_as_float(h23<<16), h3 = __uint_as_float(h23 & 0xFFFF0000u);
            uint32_t l01 = bf2pack(p0-h0, p1-h1), l23 = bf2pack(p2-h2, p3-h3);
            int c = j>>1, od = (j&1)*2;
            ph[c][od] = h01; ph[c][od+1] = h23;
            pl[c][od] = l01; pl[c][od+1] = l23;
        }

        // ---- O += P V : per d-tile jd (8 d-cols), 12 HMMA ----
        #pragma unroll
        for (int jd = 0; jd < 16; jd++){
            uint32_t va = vhs + (8*jd + l7)*STV + lhi*16;
            uint32_t wa = vls + (8*jd + l7)*STV + lhi*16;
            uint32_t vh[4][2], vl[4][2];
            #pragma unroll
            for (int c2 = 0; c2 < 2; c2++){
                uint32_t t4[4];
                ldsm4(t4, va + c2*64);
                vh[2*c2][0]=t4[0]; vh[2*c2][1]=t4[1]; vh[2*c2+1][0]=t4[2]; vh[2*c2+1][1]=t4[3];
                ldsm4(t4, wa + c2*64);
                vl[2*c2][0]=t4[0]; vl[2*c2][1]=t4[1]; vl[2*c2+1][0]=t4[2]; vl[2*c2+1][1]=t4[3];
            }
            #pragma unroll
            for (int c = 0; c < 4; c++){
                mma_bf16(o[jd], ph[c], vh[c]);
                mma_bf16(o[jd], ph[c], vl[c]);
                mma_bf16(o[jd], pl[c], vh[c]);
            }
        }
    }

    // ---- finalize: row denominators + write ----
    lsum0 += __shfl_xor_sync(0xffffffffu, lsum0, 1);
    lsum0 += __shfl_xor_sync(0xffffffffu, lsum0, 2);
    lsum1 += __shfl_xor_sync(0xffffffffu, lsum1, 1);
    lsum1 += __shfl_xor_sync(0xffffffffu, lsum1, 2);
    const float li0 = 1.0f / lsum0, li1 = 1.0f / lsum1;

    float* og0 = out + ((size_t)b*CW + rg0)*DIM;
    float* og1 = og0 + 8*DIM;
    #pragma unroll
    for (int jd = 0; jd < 16; jd++){
        int col = 8*jd + 2*lt;
        *reinterpret_cast<float2*>(og0 + col) = make_float2(o[jd][0]*li0, o[jd][1]*li0);
        *reinterpret_cast<float2*>(og1 + col) = make_float2(o[jd][2]*li1, o[jd][3]*li1);
    }
}

// ============================================================================
extern "C" void kernel_launch(void* const* d_in, const int* in_sizes, int n_in,
                              void* d_out, int out_size)
{
    (void)in_sizes; (void)n_in; (void)out_size;
    const float* x  = (const float*)d_in[0];
    const float* wq = (const float*)d_in[1];
    const float* wk = (const float*)d_in[2];
    const float* wv = (const float*)d_in[3];
    const float* R  = (const float*)d_in[4];
    float* out = (float*)d_out;

    cudaFuncSetAttribute(qkv_rope_kernel,   cudaFuncAttributeMaxDynamicSharedMemorySize, SMEM_A);
    cudaFuncSetAttribute(attn_hmma_kernel,  cudaFuncAttributeMaxDynamicSharedMemorySize, SMEM_BB);

    qkv_rope_kernel<<<dim3(32, BATCH), 256, SMEM_A>>>(x, wq, wk, wv, R);
    attn_hmma_kernel<<<128, 256, SMEM_BB>>>(out);
}

// round 8
// speedup vs baseline: 2.9679x; 1.3681x over previous
#include <cuda_runtime.h>
#include <cuda_bf16.h>
#include <cstdint>

#define CW 2048
#define DIM 128
#define BATCH 8
typedef unsigned long long ull;

__device__ __nv_bfloat16 g_qh[BATCH*CW*DIM], g_ql[BATCH*CW*DIM];
__device__ __nv_bfloat16 g_kh[BATCH*CW*DIM], g_kl[BATCH*CW*DIM];
__device__ __nv_bfloat16 g_vth[BATCH*DIM*CW], g_vtl[BATCH*DIM*CW];

// ---- helpers ----
__device__ __forceinline__ ull ld2(const float* p){ return *reinterpret_cast<const ull*>(p); }
__device__ __forceinline__ void ffma2(ull& d, ull a, ull b){
    asm("fma.rn.f32x2 %0, %1, %2, %0;" : "+l"(d) : "l"(a), "l"(b));
}
__device__ __forceinline__ float2 funpack2(ull v){
    float lo,hi; asm("mov.b64 {%0,%1}, %2;" : "=f"(lo),"=f"(hi) : "l"(v)); return make_float2(lo,hi);
}
__device__ __forceinline__ uint32_t bf2pack(float lo, float hi){   // low half <- lo
    uint32_t r; asm("cvt.rn.bf16x2.f32 %0, %1, %2;" : "=r"(r) : "f"(hi), "f"(lo)); return r;
}
__device__ __forceinline__ void cpa16s(uint32_t dst, const void* src){
    asm volatile("cp.async.cg.shared.global [%0], [%1], 16;" :: "r"(dst), "l"(src));
}
__device__ __forceinline__ void ldsm4(uint32_t* r, uint32_t a){
    asm volatile("ldmatrix.sync.aligned.m8n8.x4.shared.b16 {%0,%1,%2,%3}, [%4];"
        : "=r"(r[0]),"=r"(r[1]),"=r"(r[2]),"=r"(r[3]) : "r"(a));
}
__device__ __forceinline__ void mma_bf16(float* c, const uint32_t* a, const uint32_t* b){
    asm volatile("mma.sync.aligned.m16n8k16.row.col.f32.bf16.bf16.f32 "
        "{%0,%1,%2,%3}, {%4,%5,%6,%7}, {%8,%9}, {%0,%1,%2,%3};"
        : "+f"(c[0]),"+f"(c[1]),"+f"(c[2]),"+f"(c[3])
        : "r"(a[0]),"r"(a[1]),"r"(a[2]),"r"(a[3]),"r"(b[0]),"r"(b[1]));
}

// ============================================================================
// Kernel A: QKV projection + RoPE -> Q/K bf16 hi/lo row-major, V^T bf16 hi/lo
// (unchanged from R7)
// ============================================================================
#define XS_ST 130
#define WS_ST 130
#define CS_ST 65
#define SMEM_A ((64*XS_ST + 128*WS_ST + 2*64*CS_ST)*4)

__global__ void __launch_bounds__(256,1) qkv_rope_kernel(
    const float* __restrict__ x, const float* __restrict__ wq,
    const float* __restrict__ wk, const float* __restrict__ wv,
    const float* __restrict__ R)
{
    extern __shared__ float sm[];
    float* xs = sm;
    float* Ws = xs + 64*XS_ST;
    float* cso = Ws + 128*WS_ST;
    float* ssin = cso + 64*CS_ST;
    const int tid = threadIdx.x, b = blockIdx.y, mbase = blockIdx.x*64;

    const float* xg = x + ((size_t)b*CW + mbase)*DIM;
    for (int idx = tid; idx < 64*32; idx += 256){
        int r = idx>>5, c4 = (idx&31)*4;
        float4 v = *reinterpret_cast<const float4*>(xg + r*DIM + c4);
        float* d = xs + r*XS_ST + c4;
        d[0]=v.x; d[1]=v.y; d[2]=v.z; d[3]=v.w;
    }
    for (int idx = tid; idx < 64*64; idx += 256){
        int r = idx>>6, i = idx&63;
        const float* base = R + ((size_t)(mbase+r))*(DIM*DIM) + i*258;
        cso[r*CS_ST+i] = base[0]; ssin[r*CS_ST+i] = base[128];
    }
    const int ty = tid>>4, tx = tid&15;
    int woff[8];
    #pragma unroll
    for (int j = 0; j < 8; j++){ int p = j>>1, u = j&1; woff[j] = (2*(tx+16*p)+u)*WS_ST; }

    for (int mat = 0; mat < 3; mat++){
        __syncthreads();
        const float* w = (mat==0)?wq:(mat==1)?wk:wv;
        for (int idx = tid; idx < 128*32; idx += 256){
            int e = idx>>5, c4 = (idx&31)*4;
            float4 v = *reinterpret_cast<const float4*>(w + e*DIM + c4);
            float* d = Ws + e*WS_ST + c4;
            d[0]=v.x; d[1]=v.y; d[2]=v.z; d[3]=v.w;
        }
        __syncthreads();

        ull acc[4][8];
        #pragma unroll
        for (int i = 0; i < 4; i++){
            #pragma unroll
            for (int j = 0; j < 8; j++) acc[i][j] = 0ull;
        }
        #pragma unroll 4
        for (int d2 = 0; d2 < 64; d2++){
            ull a2[4];
            #pragma unroll
            for (int i = 0; i < 4; i++) a2[i] = ld2(xs + (4*ty+i)*XS_ST + 2*d2);
            #pragma unroll
            for (int j = 0; j < 8; j++){
                ull b2 = ld2(Ws + woff[j] + 2*d2);
                #pragma unroll
                for (int i = 0; i < 4; i++) ffma2(acc[i][j], a2[i], b2);
            }
        }
        float val[4][8];
        #pragma unroll
        for (int i = 0; i < 4; i++){
            #pragma unroll
            for (int j = 0; j < 8; j++){ float2 f = funpack2(acc[i][j]); val[i][j] = f.x + f.y; }
        }

        if (mat < 2){
            uint32_t* gh = reinterpret_cast<uint32_t*>(mat==0 ? g_qh : g_kh);
            uint32_t* gl = reinterpret_cast<uint32_t*>(mat==0 ? g_ql : g_kl);
            #pragma unroll
            for (int i = 0; i < 4; i++){
                int r = 4*ty+i;
                size_t rowp = ((size_t)b*CW + mbase + r)*64;
                #pragma unroll
                for (int p = 0; p < 4; p++){
                    int ep = tx + 16*p;
                    float c = cso[r*CS_ST+ep], s = ssin[r*CS_ST+ep];
                    float o0 =  val[i][2*p]*c + val[i][2*p+1]*s;
                    float o1 = -val[i][2*p]*s + val[i][2*p+1]*c;
                    uint32_t h = bf2pack(o0, o1);
                    float h0 = __uint_as_float(h<<16), h1 = __uint_as_float(h & 0xFFFF0000u);
                    gh[rowp+ep] = h;
                    gl[rowp+ep] = bf2pack(o0-h0, o1-h1);
                }
            }
        } else {
            __syncthreads();
            unsigned short* vth_s = reinterpret_cast<unsigned short*>(Ws);
            unsigned short* vtl_s = vth_s + 128*66;
            #pragma unroll
            for (int i = 0; i < 4; i++){
                int r = 4*ty+i;
                #pragma unroll
                for (int p = 0; p < 4; p++){
                    int ep = tx + 16*p;
                    float o0 = val[i][2*p], o1 = val[i][2*p+1];
                    uint32_t h = bf2pack(o0, o1);
                    float h0 = __uint_as_float(h<<16), h1 = __uint_as_float(h & 0xFFFF0000u);
                    uint32_t l = bf2pack(o0-h0, o1-h1);
                    vth_s[(2*ep)  *66 + r] = (unsigned short)(h & 0xFFFF);
                    vth_s[(2*ep+1)*66 + r] = (unsigned short)(h >> 16);
                    vtl_s[(2*ep)  *66 + r] = (unsigned short)(l & 0xFFFF);
                    vtl_s[(2*ep+1)*66 + r] = (unsigned short)(l >> 16);
                }
            }
            __syncthreads();
            uint32_t* gh = reinterpret_cast<uint32_t*>(g_vth);
            uint32_t* gl = reinterpret_cast<uint32_t*>(g_vtl);
            for (int idx = tid; idx < 128*32; idx += 256){
                int d = idx>>5, mp = idx&31;
                size_t dst = ((size_t)(b*DIM + d)*CW + mbase)/2 + mp;
                gh[dst] = *reinterpret_cast<uint32_t*>(&vth_s[d*66 + 2*mp]);
                gl[dst] = *reinterpret_cast<uint32_t*>(&vtl_s[d*66 + 2*mp]);
            }
        }
    }
}

// ============================================================================
// Kernel B: HMMA flash attention, BM=64, intra-CTA k-half split across warps
//   warps 0-3: k-cols [0,32) of each tile; warps 4-7: [32,64). Partial O/l
//   combined once via smem at the end (unnormalized softmax makes this exact).
// ============================================================================
#define STK 272
#define STV 144
#define KBYTES (64*STK)                  // 17408
#define VBYTES (128*STV)                 // 18432
#define QBYTES (64*STK)                  // 17408 (per hi/lo)
#define OFF_Q  0
#define OFF_B0 (2*QBYTES)                // 34816
#define OFF_B1 (OFF_B0 + 2*KBYTES + 2*VBYTES)   // 106496
#define OFF_LR (OFF_B1 + 2*KBYTES + 2*VBYTES)   // 178176
#define SMEM_BB (OFF_LR + 256)           // 178432

__device__ __forceinline__ void load_kv_stage(uint32_t sb, int b, int kt, int buf, int tid){
    const char* kh = (const char*)(g_kh  + ((size_t)b*CW + kt*64)*DIM);
    const char* kl = (const char*)(g_kl  + ((size_t)b*CW + kt*64)*DIM);
    const char* vh = (const char*)(g_vth + (size_t)b*DIM*CW + kt*64);
    const char* vl = (const char*)(g_vtl + (size_t)b*DIM*CW + kt*64);
    uint32_t bo = sb + (buf ? OFF_B1 : OFF_B0);
    #pragma unroll
    for (int t = 0; t < 4; t++){
        int c = tid + t*256;                       // K: 64 rows x 16 chunks
        int n = c>>4, cb = (c&15)*16;
        uint32_t dst = bo + n*STK + cb;
        cpa16s(dst,          kh + n*256 + cb);
        cpa16s(dst + KBYTES, kl + n*256 + cb);
    }
    #pragma unroll
    for (int t = 0; t < 4; t++){
        int c = tid + t*256;                       // V^T: 128 rows x 8 chunks
        int d = c>>3, cb = (c&7)*16;
        uint32_t dst = bo + 2*KBYTES + d*STV + cb;
        cpa16s(dst,          vh + (size_t)d*CW*2 + cb);
        cpa16s(dst + VBYTES, vl + (size_t)d*CW*2 + cb);
    }
}

__global__ void __launch_bounds__(256,1) attn_hmma_kernel(float* __restrict__ out)
{
    extern __shared__ char smc[];
    const uint32_t sb = (uint32_t)__cvta_generic_to_shared(smc);
    const int tid = threadIdx.x, wid = tid>>5, lane = tid&31;
    const int b = blockIdx.x & 7;
    const int qt = 31 - ((int)blockIdx.x >> 3);    // heavy q-tiles first
    const int qbase = qt*64;
    const int ktmax = qt;                           // inclusive
    const int wg = wid & 3;                         // row block (16 rows)
    const int nh = wid >> 2;                        // k-half (0/1)
    const int l7 = lane & 7, lhi = lane >> 3;
    const int lg = lane >> 2, lt = lane & 3;
    const int row0 = 16*wg + lg;                    // tile-local row (c0/c1); c2/c3: +8

    // ---- prologue: stage Q (dedicated region) + K/V tile0 ----
    {
        const char* qh = (const char*)(g_qh + ((size_t)b*CW + qbase)*DIM);
        const char* ql = (const char*)(g_ql + ((size_t)b*CW + qbase)*DIM);
        #pragma unroll
        for (int t = 0; t < 4; t++){
            int c = tid + t*256;                   // 64 rows x 16 chunks
            int n = c>>4, cb = (c&15)*16;
            uint32_t dst = sb + OFF_Q + n*STK + cb;
            cpa16s(dst,          qh + n*256 + cb);
            cpa16s(dst + QBYTES, ql + n*256 + cb);
        }
        asm volatile("cp.async.commit_group;");    // G0: Q
        load_kv_stage(sb, b, 0, 0, tid);
        asm volatile("cp.async.commit_group;");    // G1: tile0
    }
    asm volatile("cp.async.wait_group 1;");        // Q landed
    __syncthreads();

    // Q A-fragments (8 k-chunks, hi+lo) — 16 rows per warp
    uint32_t qh[8][4], ql[8][4];
    {
        uint32_t qa = sb + OFF_Q + (16*wg + (lane&15))*STK + (lane>>4)*16;
        #pragma unroll
        for (int c = 0; c < 8; c++){
            ldsm4(qh[c], qa + c*32);
            ldsm4(ql[c], qa + QBYTES + c*32);
        }
    }

    float o[16][4];
    #pragma unroll
    for (int jd = 0; jd < 16; jd++){
        #pragma unroll
        for (int i = 0; i < 4; i++) o[jd][i] = 0.0f;
    }
    float lsum0 = 0.0f, lsum1 = 0.0f;
    const float sc = 0.08838834764831845f;         // 1/sqrt(128)

    for (int kt = 0; kt <= ktmax; kt++){
        __syncthreads();                            // prior reads of buf[(kt+1)&1] done
        if (kt < ktmax) load_kv_stage(sb, b, kt+1, (kt+1)&1, tid);
        asm volatile("cp.async.commit_group;");
        asm volatile("cp.async.wait_group 1;");     // stage kt landed
        __syncthreads();

        const uint32_t bo = sb + ((kt&1) ? OFF_B1 : OFF_B0);
        const uint32_t khs = bo, kls = bo + KBYTES;
        const uint32_t vhs = bo + 2*KBYTES, vls = vhs + VBYTES;

        // ---- S = Q K^T : warp covers 4 n-tiles (k-cols nh*32 .. +32) ----
        //      two independent accumulator chains per tile (hh | hl+lh)
        float shh[4][4], sxx[4][4];
        #pragma unroll
        for (int j = 0; j < 4; j++){
            #pragma unroll
            for (int i = 0; i < 4; i++){ shh[j][i] = 0.0f; sxx[j][i] = 0.0f; }
            const int jj = 4*nh + j;
            uint32_t ka = khs + (8*jj + l7)*STK + lhi*16;
            uint32_t la = kls + (8*jj + l7)*STK + lhi*16;
            #pragma unroll
            for (int c2 = 0; c2 < 4; c2++){
                uint32_t th[4], tl[4];
                ldsm4(th, ka + c2*64);
                ldsm4(tl, la + c2*64);
                uint32_t bhA[2] = {th[0], th[1]}, bhB[2] = {th[2], th[3]};
                uint32_t blA[2] = {tl[0], tl[1]}, blB[2] = {tl[2], tl[3]};
                mma_bf16(shh[j], qh[2*c2],   bhA);
                mma_bf16(shh[j], qh[2*c2+1], bhB);
                mma_bf16(sxx[j], qh[2*c2],   blA);
                mma_bf16(sxx[j], qh[2*c2+1], blB);
                mma_bf16(sxx[j], ql[2*c2],   bhA);
                mma_bf16(sxx[j], ql[2*c2+1], bhB);
            }
        }

        // ---- softmax (unnormalized) + repack into P A-fragments ----
        const bool domask = (kt == ktmax);
        uint32_t ph[2][4], pl[2][4];
        #pragma unroll
        for (int j = 0; j < 4; j++){
            const int colLoc = 32*nh + 8*j + 2*lt;
            float p0 = __expf((shh[j][0] + sxx[j][0])*sc);
            float p1 = __expf((shh[j][1] + sxx[j][1])*sc);
            float p2 = __expf((shh[j][2] + sxx[j][2])*sc);
            float p3 = __expf((shh[j][3] + sxx[j][3])*sc);
            if (domask){
                if (colLoc   > row0)     p0 = 0.0f;
                if (colLoc+1 > row0)     p1 = 0.0f;
                if (colLoc   > row0+8)   p2 = 0.0f;
                if (colLoc+1 > row0+8)   p3 = 0.0f;
            }
            lsum0 += p0 + p1;
            lsum1 += p2 + p3;
            uint32_t h01 = bf2pack(p0, p1), h23 = bf2pack(p2, p3);
            float h0 = __uint_as_float(h01<<16), h1 = __uint_as_float(h01 & 0xFFFF0000u);
            float h2 = __uint_as_float(h23<<16), h3 = __uint_as_float(h23 & 0xFFFF0000u);
            uint32_t l01 = bf2pack(p0-h0, p1-h1), l23 = bf2pack(p2-h2, p3-h3);
            int c = j>>1, od = (j&1)*2;
            ph[c][od] = h01; ph[c][od+1] = h23;
            pl[c][od] = l01; pl[c][od+1] = l23;
        }

        // ---- O += P V : warp's k-half only (chunk pair c2 = nh) ----
        #pragma unroll
        for (int jd = 0; jd < 16; jd++){
            uint32_t va = vhs + (8*jd + l7)*STV + lhi*16 + nh*64;
            uint32_t wa = vls + (8*jd + l7)*STV + lhi*16 + nh*64;
            uint32_t tv[4], tw[4];
            ldsm4(tv, va);
            ldsm4(tw, wa);
            uint32_t vhA[2] = {tv[0], tv[1]}, vhB[2] = {tv[2], tv[3]};
            uint32_t vlA[2] = {tw[0], tw[1]}, vlB[2] = {tw[2], tw[3]};
            mma_bf16(o[jd], ph[0], vhA);
            mma_bf16(o[jd], ph[1], vhB);
            mma_bf16(o[jd], ph[0], vlA);
            mma_bf16(o[jd], ph[1], vlB);
            mma_bf16(o[jd], pl[0], vhA);
            mma_bf16(o[jd], pl[1], vhB);
        }
    }

    // ---- combine the two k-halves via smem, then write ----
    lsum0 += __shfl_xor_sync(0xffffffffu, lsum0, 1);
    lsum0 += __shfl_xor_sync(0xffffffffu, lsum0, 2);
    lsum1 += __shfl_xor_sync(0xffffffffu, lsum1, 1);
    lsum1 += __shfl_xor_sync(0xffffffffu, lsum1, 2);

    __syncthreads();                               // all buf reads done; reuse buf0
    float* xch = reinterpret_cast<float*>(smc + OFF_B0);   // [64][132]
    float* lr  = reinterpret_cast<float*>(smc + OFF_LR);   // [64]
    if (nh == 1){
        #pragma unroll
        for (int jd = 0; jd < 16; jd++){
            int col = 8*jd + 2*lt;
            *reinterpret_cast<float2*>(&xch[row0*132 + col])     = make_float2(o[jd][0], o[jd][1]);
            *reinterpret_cast<float2*>(&xch[(row0+8)*132 + col]) = make_float2(o[jd][2], o[jd][3]);
        }
        if (lt == 0){ lr[row0] = lsum0; lr[row0+8] = lsum1; }
    }
    __syncthreads();
    if (nh == 0){
        const float li0 = 1.0f / (lsum0 + lr[row0]);
        const float li1 = 1.0f / (lsum1 + lr[row0+8]);
        float* og0 = out + ((size_t)b*CW + qbase + row0)*DIM;
        float* og1 = og0 + 8*DIM;
        #pragma unroll
        for (int jd = 0; jd < 16; jd++){
            int col = 8*jd + 2*lt;
            float2 a = *reinterpret_cast<float2*>(&xch[row0*132 + col]);
            float2 c = *reinterpret_cast<float2*>(&xch[(row0+8)*132 + col]);
            *reinterpret_cast<float2*>(og0 + col) = make_float2((o[jd][0]+a.x)*li0, (o[jd][1]+a.y)*li0);
            *reinterpret_cast<float2*>(og1 + col) = make_float2((o[jd][2]+c.x)*li1, (o[jd][3]+c.y)*li1);
        }
    }
}

// ============================================================================
extern "C" void kernel_launch(void* const* d_in, const int* in_sizes, int n_in,
                              void* d_out, int out_size)
{
    (void)in_sizes; (void)n_in; (void)out_size;
    const float* x  = (const float*)d_in[0];
    const float* wq = (const float*)d_in[1];
    const float* wk = (const float*)d_in[2];
    const float* wv = (const float*)d_in[3];
    const float* R  = (const float*)d_in[4];
    float* out = (float*)d_out;

    cudaFuncSetAttribute(qkv_rope_kernel,   cudaFuncAttributeMaxDynamicSharedMemorySize, SMEM_A);
    cudaFuncSetAttribute(attn_hmma_kernel,  cudaFuncAttributeMaxDynamicSharedMemorySize, SMEM_BB);

    qkv_rope_kernel<<<dim3(32, BATCH), 256, SMEM_A>>>(x, wq, wk, wv, R);
    attn_hmma_kernel<<<256, 256, SMEM_BB>>>(out);
}

// round 9
// speedup vs baseline: 3.2927x; 1.1094x over previous
#include <cuda_runtime.h>
#include <cuda_bf16.h>
#include <cstdint>

#define CW 2048
#define DIM 128
#define BATCH 8
typedef unsigned long long ull;

__device__ __nv_bfloat16 g_qh[BATCH*CW*DIM], g_ql[BATCH*CW*DIM];
__device__ __nv_bfloat16 g_kh[BATCH*CW*DIM], g_kl[BATCH*CW*DIM];
__device__ __nv_bfloat16 g_vth[BATCH*DIM*CW], g_vtl[BATCH*DIM*CW];
__device__ float g_cos[CW*64], g_sin[CW*64];

// ---- helpers ----
__device__ __forceinline__ ull ld2(const float* p){ return *reinterpret_cast<const ull*>(p); }
__device__ __forceinline__ void ffma2(ull& d, ull a, ull b){
    asm("fma.rn.f32x2 %0, %1, %2, %0;" : "+l"(d) : "l"(a), "l"(b));
}
__device__ __forceinline__ float2 funpack2(ull v){
    float lo,hi; asm("mov.b64 {%0,%1}, %2;" : "=f"(lo),"=f"(hi) : "l"(v)); return make_float2(lo,hi);
}
__device__ __forceinline__ uint32_t bf2pack(float lo, float hi){   // low half <- lo
    uint32_t r; asm("cvt.rn.bf16x2.f32 %0, %1, %2;" : "=r"(r) : "f"(hi), "f"(lo)); return r;
}
__device__ __forceinline__ void cpa16s(uint32_t dst, const void* src){
    asm volatile("cp.async.cg.shared.global [%0], [%1], 16;" :: "r"(dst), "l"(src));
}
__device__ __forceinline__ void ldsm4(uint32_t* r, uint32_t a){
    asm volatile("ldmatrix.sync.aligned.m8n8.x4.shared.b16 {%0,%1,%2,%3}, [%4];"
        : "=r"(r[0]),"=r"(r[1]),"=r"(r[2]),"=r"(r[3]) : "r"(a));
}
__device__ __forceinline__ void mma_bf16(float* c, const uint32_t* a, const uint32_t* b){
    asm volatile("mma.sync.aligned.m16n8k16.row.col.f32.bf16.bf16.f32 "
        "{%0,%1,%2,%3}, {%4,%5,%6,%7}, {%8,%9}, {%0,%1,%2,%3};"
        : "+f"(c[0]),"+f"(c[1]),"+f"(c[2]),"+f"(c[3])
        : "r"(a[0]),"r"(a[1]),"r"(a[2]),"r"(a[3]),"r"(b[0]),"r"(b[1]));
}

// ============================================================================
// Kernel R: gather RoPE cos/sin from R's 2x2 block diagonal (one-time, tiny)
// ============================================================================
__global__ void __launch_bounds__(512,2) rope_gather(const float* __restrict__ R)
{
    int idx = blockIdx.x*512 + threadIdx.x;       // 0 .. 2048*64-1
    int m = idx >> 6, i = idx & 63;
    const float* base = R + (size_t)m*(DIM*DIM) + i*258;
    g_cos[idx] = base[0];
    g_sin[idx] = base[128];
}

// ============================================================================
// Kernel A: projection (+RoPE for Q/K) — ONE matrix per CTA, 2 CTAs/SM
// ============================================================================
#define XS_ST 130
#define WS_ST 130
#define SMEM_A ((64*XS_ST + 128*WS_ST)*4)   // 99840 B -> 2 CTAs/SM

__global__ void __launch_bounds__(256,2) qkv_rope_kernel(
    const float* __restrict__ x, const float* __restrict__ wq,
    const float* __restrict__ wk, const float* __restrict__ wv)
{
    extern __shared__ float sm[];
    float* xs = sm;                     // [64][130]
    float* Ws = xs + 64*XS_ST;          // [128][130]
    const int tid = threadIdx.x, b = blockIdx.y, mbase = blockIdx.x*64;
    const int mat = blockIdx.z;

    const float* xg = x + ((size_t)b*CW + mbase)*DIM;
    for (int idx = tid; idx < 64*32; idx += 256){
        int r = idx>>5, c4 = (idx&31)*4;
        float4 v = *reinterpret_cast<const float4*>(xg + r*DIM + c4);
        float* d = xs + r*XS_ST + c4;
        d[0]=v.x; d[1]=v.y; d[2]=v.z; d[3]=v.w;
    }
    const float* w = (mat==0)?wq:(mat==1)?wk:wv;
    for (int idx = tid; idx < 128*32; idx += 256){
        int e = idx>>5, c4 = (idx&31)*4;
        float4 v = *reinterpret_cast<const float4*>(w + e*DIM + c4);
        float* d = Ws + e*WS_ST + c4;
        d[0]=v.x; d[1]=v.y; d[2]=v.z; d[3]=v.w;
    }
    __syncthreads();

    const int ty = tid>>4, tx = tid&15;
    int woff[8];
    #pragma unroll
    for (int j = 0; j < 8; j++){ int p = j>>1, u = j&1; woff[j] = (2*(tx+16*p)+u)*WS_ST; }

    ull acc[4][8];
    #pragma unroll
    for (int i = 0; i < 4; i++){
        #pragma unroll
        for (int j = 0; j < 8; j++) acc[i][j] = 0ull;
    }
    #pragma unroll 4
    for (int d2 = 0; d2 < 64; d2++){
        ull a2[4];
        #pragma unroll
        for (int i = 0; i < 4; i++) a2[i] = ld2(xs + (4*ty+i)*XS_ST + 2*d2);
        #pragma unroll
        for (int j = 0; j < 8; j++){
            ull b2 = ld2(Ws + woff[j] + 2*d2);
            #pragma unroll
            for (int i = 0; i < 4; i++) ffma2(acc[i][j], a2[i], b2);
        }
    }
    float val[4][8];
    #pragma unroll
    for (int i = 0; i < 4; i++){
        #pragma unroll
        for (int j = 0; j < 8; j++){ float2 f = funpack2(acc[i][j]); val[i][j] = f.x + f.y; }
    }

    if (mat < 2){   // Q or K: rope (coefs from g_cos/g_sin) + hi/lo split
        uint32_t* gh = reinterpret_cast<uint32_t*>(mat==0 ? g_qh : g_kh);
        uint32_t* gl = reinterpret_cast<uint32_t*>(mat==0 ? g_ql : g_kl);
        #pragma unroll
        for (int i = 0; i < 4; i++){
            int r = 4*ty+i;
            const float* cr = g_cos + (size_t)(mbase + r)*64;
            const float* sr = g_sin + (size_t)(mbase + r)*64;
            size_t rowp = ((size_t)b*CW + mbase + r)*64;
            #pragma unroll
            for (int p = 0; p < 4; p++){
                int ep = tx + 16*p;
                float c = __ldg(cr + ep), s = __ldg(sr + ep);
                float o0 =  val[i][2*p]*c + val[i][2*p+1]*s;
                float o1 = -val[i][2*p]*s + val[i][2*p+1]*c;
                uint32_t h = bf2pack(o0, o1);
                float h0 = __uint_as_float(h<<16), h1 = __uint_as_float(h & 0xFFFF0000u);
                gh[rowp+ep] = h;
                gl[rowp+ep] = bf2pack(o0-h0, o1-h1);
            }
        }
    } else {        // V: transpose via smem staging (overlaid on Ws), hi/lo split
        __syncthreads();
        unsigned short* vth_s = reinterpret_cast<unsigned short*>(Ws);
        unsigned short* vtl_s = vth_s + 128*66;
        #pragma unroll
        for (int i = 0; i < 4; i++){
            int r = 4*ty+i;
            #pragma unroll
            for (int p = 0; p < 4; p++){
                int ep = tx + 16*p;
                float o0 = val[i][2*p], o1 = val[i][2*p+1];
                uint32_t h = bf2pack(o0, o1);
                float h0 = __uint_as_float(h<<16), h1 = __uint_as_float(h & 0xFFFF0000u);
                uint32_t l = bf2pack(o0-h0, o1-h1);
                vth_s[(2*ep)  *66 + r] = (unsigned short)(h & 0xFFFF);
                vth_s[(2*ep+1)*66 + r] = (unsigned short)(h >> 16);
                vtl_s[(2*ep)  *66 + r] = (unsigned short)(l & 0xFFFF);
                vtl_s[(2*ep+1)*66 + r] = (unsigned short)(l >> 16);
            }
        }
        __syncthreads();
        uint32_t* gh = reinterpret_cast<uint32_t*>(g_vth);
        uint32_t* gl = reinterpret_cast<uint32_t*>(g_vtl);
        for (int idx = tid; idx < 128*32; idx += 256){
            int d = idx>>5, mp = idx&31;
            size_t dst = ((size_t)(b*DIM + d)*CW + mbase)/2 + mp;
            gh[dst] = *reinterpret_cast<uint32_t*>(&vth_s[d*66 + 2*mp]);
            gl[dst] = *reinterpret_cast<uint32_t*>(&vtl_s[d*66 + 2*mp]);
        }
    }
}

// ============================================================================
// Kernel B: HMMA flash attention, BM=64, intra-CTA k-half split (R8, unchanged)
// ============================================================================
#define STK 272
#define STV 144
#define KBYTES (64*STK)
#define VBYTES (128*STV)
#define QBYTES (64*STK)
#define OFF_Q  0
#define OFF_B0 (2*QBYTES)
#define OFF_B1 (OFF_B0 + 2*KBYTES + 2*VBYTES)
#define OFF_LR (OFF_B1 + 2*KBYTES + 2*VBYTES)
#define SMEM_BB (OFF_LR + 256)

__device__ __forceinline__ void load_kv_stage(uint32_t sb, int b, int kt, int buf, int tid){
    const char* kh = (const char*)(g_kh  + ((size_t)b*CW + kt*64)*DIM);
    const char* kl = (const char*)(g_kl  + ((size_t)b*CW + kt*64)*DIM);
    const char* vh = (const char*)(g_vth + (size_t)b*DIM*CW + kt*64);
    const char* vl = (const char*)(g_vtl + (size_t)b*DIM*CW + kt*64);
    uint32_t bo = sb + (buf ? OFF_B1 : OFF_B0);
    #pragma unroll
    for (int t = 0; t < 4; t++){
        int c = tid + t*256;
        int n = c>>4, cb = (c&15)*16;
        uint32_t dst = bo + n*STK + cb;
        cpa16s(dst,          kh + n*256 + cb);
        cpa16s(dst + KBYTES, kl + n*256 + cb);
    }
    #pragma unroll
    for (int t = 0; t < 4; t++){
        int c = tid + t*256;
        int d = c>>3, cb = (c&7)*16;
        uint32_t dst = bo + 2*KBYTES + d*STV + cb;
        cpa16s(dst,          vh + (size_t)d*CW*2 + cb);
        cpa16s(dst + VBYTES, vl + (size_t)d*CW*2 + cb);
    }
}

__global__ void __launch_bounds__(256,1) attn_hmma_kernel(float* __restrict__ out)
{
    extern __shared__ char smc[];
    const uint32_t sb = (uint32_t)__cvta_generic_to_shared(smc);
    const int tid = threadIdx.x, wid = tid>>5, lane = tid&31;
    const int b = blockIdx.x & 7;
    const int qt = 31 - ((int)blockIdx.x >> 3);
    const int qbase = qt*64;
    const int ktmax = qt;
    const int wg = wid & 3;
    const int nh = wid >> 2;
    const int l7 = lane & 7, lhi = lane >> 3;
    const int lg = lane >> 2, lt = lane & 3;
    const int row0 = 16*wg + lg;

    {
        const char* qh = (const char*)(g_qh + ((size_t)b*CW + qbase)*DIM);
        const char* ql = (const char*)(g_ql + ((size_t)b*CW + qbase)*DIM);
        #pragma unroll
        for (int t = 0; t < 4; t++){
            int c = tid + t*256;
            int n = c>>4, cb = (c&15)*16;
            uint32_t dst = sb + OFF_Q + n*STK + cb;
            cpa16s(dst,          qh + n*256 + cb);
            cpa16s(dst + QBYTES, ql + n*256 + cb);
        }
        asm volatile("cp.async.commit_group;");
        load_kv_stage(sb, b, 0, 0, tid);
        asm volatile("cp.async.commit_group;");
    }
    asm volatile("cp.async.wait_group 1;");
    __syncthreads();

    uint32_t qh[8][4], ql[8][4];
    {
        uint32_t qa = sb + OFF_Q + (16*wg + (lane&15))*STK + (lane>>4)*16;
        #pragma unroll
        for (int c = 0; c < 8; c++){
            ldsm4(qh[c], qa + c*32);
            ldsm4(ql[c], qa + QBYTES + c*32);
        }
    }

    float o[16][4];
    #pragma unroll
    for (int jd = 0; jd < 16; jd++){
        #pragma unroll
        for (int i = 0; i < 4; i++) o[jd][i] = 0.0f;
    }
    float lsum0 = 0.0f, lsum1 = 0.0f;
    const float sc = 0.08838834764831845f;

    for (int kt = 0; kt <= ktmax; kt++){
        __syncthreads();
        if (kt < ktmax) load_kv_stage(sb, b, kt+1, (kt+1)&1, tid);
        asm volatile("cp.async.commit_group;");
        asm volatile("cp.async.wait_group 1;");
        __syncthreads();

        const uint32_t bo = sb + ((kt&1) ? OFF_B1 : OFF_B0);
        const uint32_t khs = bo, kls = bo + KBYTES;
        const uint32_t vhs = bo + 2*KBYTES, vls = vhs + VBYTES;

        float shh[4][4], sxx[4][4];
        #pragma unroll
        for (int j = 0; j < 4; j++){
            #pragma unroll
            for (int i = 0; i < 4; i++){ shh[j][i] = 0.0f; sxx[j][i] = 0.0f; }
            const int jj = 4*nh + j;
            uint32_t ka = khs + (8*jj + l7)*STK + lhi*16;
            uint32_t la = kls + (8*jj + l7)*STK + lhi*16;
            #pragma unroll
            for (int c2 = 0; c2 < 4; c2++){
                uint32_t th[4], tl[4];
                ldsm4(th, ka + c2*64);
                ldsm4(tl, la + c2*64);
                uint32_t bhA[2] = {th[0], th[1]}, bhB[2] = {th[2], th[3]};
                uint32_t blA[2] = {tl[0], tl[1]}, blB[2] = {tl[2], tl[3]};
                mma_bf16(shh[j], qh[2*c2],   bhA);
                mma_bf16(shh[j], qh[2*c2+1], bhB);
                mma_bf16(sxx[j], qh[2*c2],   blA);
                mma_bf16(sxx[j], qh[2*c2+1], blB);
                mma_bf16(sxx[j], ql[2*c2],   bhA);
                mma_bf16(sxx[j], ql[2*c2+1], bhB);
            }
        }

        const bool domask = (kt == ktmax);
        uint32_t ph[2][4], pl[2][4];
        #pragma unroll
        for (int j = 0; j < 4; j++){
            const int colLoc = 32*nh + 8*j + 2*lt;
            float p0 = __expf((shh[j][0] + sxx[j][0])*sc);
            float p1 = __expf((shh[j][1] + sxx[j][1])*sc);
            float p2 = __expf((shh[j][2] + sxx[j][2])*sc);
            float p3 = __expf((shh[j][3] + sxx[j][3])*sc);
            if (domask){
                if (colLoc   > row0)     p0 = 0.0f;
                if (colLoc+1 > row0)     p1 = 0.0f;
                if (colLoc   > row0+8)   p2 = 0.0f;
                if (colLoc+1 > row0+8)   p3 = 0.0f;
            }
            lsum0 += p0 + p1;
            lsum1 += p2 + p3;
            uint32_t h01 = bf2pack(p0, p1), h23 = bf2pack(p2, p3);
            float h0 = __uint_as_float(h01<<16), h1 = __uint_as_float(h01 & 0xFFFF0000u);
            float h2 = __uint_as_float(h23<<16), h3 = __uint_as_float(h23 & 0xFFFF0000u);
            uint32_t l01 = bf2pack(p0-h0, p1-h1), l23 = bf2pack(p2-h2, p3-h3);
            int c = j>>1, od = (j&1)*2;
            ph[c][od] = h01; ph[c][od+1] = h23;
            pl[c][od] = l01; pl[c][od+1] = l23;
        }

        #pragma unroll
        for (int jd = 0; jd < 16; jd++){
            uint32_t va = vhs + (8*jd + l7)*STV + lhi*16 + nh*64;
            uint32_t wa = vls + (8*jd + l7)*STV + lhi*16 + nh*64;
            uint32_t tv[4], tw[4];
            ldsm4(tv, va);
            ldsm4(tw, wa);
            uint32_t vhA[2] = {tv[0], tv[1]}, vhB[2] = {tv[2], tv[3]};
            uint32_t vlA[2] = {tw[0], tw[1]}, vlB[2] = {tw[2], tw[3]};
            mma_bf16(o[jd], ph[0], vhA);
            mma_bf16(o[jd], ph[1], vhB);
            mma_bf16(o[jd], ph[0], vlA);
            mma_bf16(o[jd], ph[1], vlB);
            mma_bf16(o[jd], pl[0], vhA);
            mma_bf16(o[jd], pl[1], vhB);
        }
    }

    lsum0 += __shfl_xor_sync(0xffffffffu, lsum0, 1);
    lsum0 += __shfl_xor_sync(0xffffffffu, lsum0, 2);
    lsum1 += __shfl_xor_sync(0xffffffffu, lsum1, 1);
    lsum1 += __shfl_xor_sync(0xffffffffu, lsum1, 2);

    __syncthreads();
    float* xch = reinterpret_cast<float*>(smc + OFF_B0);
    float* lr  = reinterpret_cast<float*>(smc + OFF_LR);
    if (nh == 1){
        #pragma unroll
        for (int jd = 0; jd < 16; jd++){
            int col = 8*jd + 2*lt;
            *reinterpret_cast<float2*>(&xch[row0*132 + col])     = make_float2(o[jd][0], o[jd][1]);
            *reinterpret_cast<float2*>(&xch[(row0+8)*132 + col]) = make_float2(o[jd][2], o[jd][3]);
        }
        if (lt == 0){ lr[row0] = lsum0; lr[row0+8] = lsum1; }
    }
    __syncthreads();
    if (nh == 0){
        const float li0 = 1.0f / (lsum0 + lr[row0]);
        const float li1 = 1.0f / (lsum1 + lr[row0+8]);
        float* og0 = out + ((size_t)b*CW + qbase + row0)*DIM;
        float* og1 = og0 + 8*DIM;
        #pragma unroll
        for (int jd = 0; jd < 16; jd++){
            int col = 8*jd + 2*lt;
            float2 a = *reinterpret_cast<float2*>(&xch[row0*132 + col]);
            float2 c = *reinterpret_cast<float2*>(&xch[(row0+8)*132 + col]);
            *reinterpret_cast<float2*>(og0 + col) = make_float2((o[jd][0]+a.x)*li0, (o[jd][1]+a.y)*li0);
            *reinterpret_cast<float2*>(og1 + col) = make_float2((o[jd][2]+c.x)*li1, (o[jd][3]+c.y)*li1);
        }
    }
}

// ============================================================================
extern "C" void kernel_launch(void* const* d_in, const int* in_sizes, int n_in,
                              void* d_out, int out_size)
{
    (void)in_sizes; (void)n_in; (void)out_size;
    const float* x  = (const float*)d_in[0];
    const float* wq = (const float*)d_in[1];
    const float* wk = (const float*)d_in[2];
    const float* wv = (const float*)d_in[3];
    const float* R  = (const float*)d_in[4];
    float* out = (float*)d_out;

    cudaFuncSetAttribute(qkv_rope_kernel,   cudaFuncAttributeMaxDynamicSharedMemorySize, SMEM_A);
    cudaFuncSetAttribute(attn_hmma_kernel,  cudaFuncAttributeMaxDynamicSharedMemorySize, SMEM_BB);

    rope_gather<<<256, 512>>>(R);
    qkv_rope_kernel<<<dim3(32, BATCH, 3), 256, SMEM_A>>>(x, wq, wk, wv);
    attn_hmma_kernel<<<256, 256, SMEM_BB>>>(out);
}